// round 7
// baseline (speedup 1.0000x reference)
#include <cuda_runtime.h>
#include <cstdint>

#define SEQ   4096
#define EMB   1024
#define NH    16
#define HD    64
#define WIN   256
#define QKV_N 3072

// ---- attention tiling (round-4 proven) ----
#define LQ 68
#define LV 72
#define ATTN_SMEM ((3 * 64 * LQ + 64 * LV) * 4)

// ---- int8 GEMM tiling ----
#define IBK   64
#define LDW   20                     // words per smem row (80 B: 64 data + 16 pad)
#define BUFW  (128 * LDW)            // words per digit buffer (2560)
#define STGW  (4 * BUFW)             // words per stage (A1,A2,B1,B2) = 10240 (40 KB)
#define ISTG  3
#define I8_SMEM (ISTG * STGW * 4)    // 120 KB

static __device__ float  g_qkv[SEQ * QKV_N];      // fp32 q|k|v
static __device__ float  g_ctx[SEQ * EMB];        // attention out fp32
static __device__ int8_t g_x1[SEQ * EMB];         // x digit1
static __device__ int8_t g_x2[SEQ * EMB];         // x digit2
static __device__ int8_t g_c1[SEQ * EMB];         // ctx digit1
static __device__ int8_t g_c2[SEQ * EMB];         // ctx digit2
static __device__ int8_t g_bq1[QKV_N * EMB];      // w_qkv^T digits [N][K]
static __device__ int8_t g_bq2[QKV_N * EMB];
static __device__ int8_t g_bo1[EMB * EMB];        // w_out^T digits
static __device__ int8_t g_bo2[EMB * EMB];
static __device__ float  g_sax[SEQ], g_sac[SEQ];            // row scales
static __device__ float  g_sbq[QKV_N], g_sbqi[QKV_N];       // col scales (+inv)
static __device__ float  g_sbo[EMB], g_sboi[EMB];

// ===========================================================================
__device__ __forceinline__ uint32_t f2tf(float x) {
    uint32_t r;
    asm("cvt.rna.tf32.f32 %0, %1;" : "=r"(r) : "f"(x));
    return r;
}
__device__ __forceinline__ void mma_tf32(float d[4], const uint32_t a[4], const uint32_t b[2]) {
    asm volatile(
        "mma.sync.aligned.m16n8k8.row.col.f32.tf32.tf32.f32 "
        "{%0,%1,%2,%3}, {%4,%5,%6,%7}, {%8,%9}, {%0,%1,%2,%3};\n"
        : "+f"(d[0]), "+f"(d[1]), "+f"(d[2]), "+f"(d[3])
        : "r"(a[0]), "r"(a[1]), "r"(a[2]), "r"(a[3]), "r"(b[0]), "r"(b[1]));
}
__device__ __forceinline__ void mma_s8(int d[4], const uint32_t a[4], const uint32_t b[2]) {
    asm volatile(
        "mma.sync.aligned.m16n8k32.row.col.s32.s8.s8.s32 "
        "{%0,%1,%2,%3}, {%4,%5,%6,%7}, {%8,%9}, {%0,%1,%2,%3};\n"
        : "+r"(d[0]), "+r"(d[1]), "+r"(d[2]), "+r"(d[3])
        : "r"(a[0]), "r"(a[1]), "r"(a[2]), "r"(a[3]), "r"(b[0]), "r"(b[1]));
}
__device__ __forceinline__ void cp16(void* smem_dst, const void* gsrc) {
    uint32_t saddr;
    asm("{ .reg .u64 t; cvta.to.shared.u64 t, %1; cvt.u32.u64 %0, t; }" : "=r"(saddr) : "l"(smem_dst));
    asm volatile("cp.async.cg.shared.global [%0], [%1], 16;\n" :: "r"(saddr), "l"(gsrc) : "memory");
}

// ===========================================================================
// quant_rows: S[M,1024] fp32 -> per-row scale + 2 int8 digit arrays.
// One 256-thread block per row.
// ===========================================================================
__global__ __launch_bounds__(256) void quant_rows(const float* __restrict__ S,
                                                  int8_t* __restrict__ D1,
                                                  int8_t* __restrict__ D2,
                                                  float* __restrict__ sa) {
    __shared__ float red[8];
    const int row = blockIdx.x, t = threadIdx.x;
    const float* r = S + (size_t)row * 1024;
    float v[4], m = 0.0f;
#pragma unroll
    for (int i = 0; i < 4; i++) {
        v[i] = r[t + 256 * i];
        m = fmaxf(m, fabsf(v[i]));
    }
#pragma unroll
    for (int off = 16; off; off >>= 1) m = fmaxf(m, __shfl_xor_sync(~0u, m, off));
    if ((t & 31) == 0) red[t >> 5] = m;
    __syncthreads();
    m = red[t & 7];
#pragma unroll
    for (int off = 4; off; off >>= 1) m = fmaxf(m, __shfl_xor_sync(~0u, m, off));
    m = fmaxf(m, 1e-20f);
    const float inv = 126.0f / m;
    if (t == 0) sa[row] = m * (1.0f / 126.0f);
#pragma unroll
    for (int i = 0; i < 4; i++) {
        float q = v[i] * inv;
        int q1 = __float2int_rn(q);
        int q2 = __float2int_rn((q - (float)q1) * 128.0f);
        D1[(size_t)row * 1024 + t + 256 * i] = (int8_t)q1;
        D2[(size_t)row * 1024 + t + 256 * i] = (int8_t)q2;
    }
}

// ===========================================================================
// colmax: W[1024,N] -> per-column absmax scale (+inverse). Block: 32 cols x 8 k-groups.
// ===========================================================================
__global__ __launch_bounds__(256) void colmax(const float* __restrict__ W,
                                              float* __restrict__ sb,
                                              float* __restrict__ sbi, int N) {
    __shared__ float red[8][32];
    const int tx = threadIdx.x & 31, ty = threadIdx.x >> 5;
    const int c = blockIdx.x * 32 + tx;
    float m = 1e-20f;
    const float* p = W + (size_t)(ty * 128) * N + c;
#pragma unroll 4
    for (int k = 0; k < 128; k++) m = fmaxf(m, fabsf(p[(size_t)k * N]));
    red[ty][tx] = m;
    __syncthreads();
    if (ty == 0) {
#pragma unroll
        for (int j = 1; j < 8; j++) m = fmaxf(m, red[j][tx]);
        sb[c]  = m * (1.0f / 126.0f);
        sbi[c] = 126.0f / m;
    }
}

// ===========================================================================
// tq: transpose + 2-digit quantize: W[1024,N] -> BT1/BT2 [N][1024] int8.
// ===========================================================================
__global__ __launch_bounds__(256) void tq(const float* __restrict__ W,
                                          const float* __restrict__ sbi,
                                          int8_t* __restrict__ T1,
                                          int8_t* __restrict__ T2, int N) {
    __shared__ float tile[32][33];
    const int tx = threadIdx.x & 31, ty = threadIdx.x >> 5;
    const int n0 = blockIdx.x * 32, k0 = blockIdx.y * 32;
#pragma unroll
    for (int i = 0; i < 4; i++)
        tile[ty + 8 * i][tx] = W[(size_t)(k0 + ty + 8 * i) * N + n0 + tx];
    __syncthreads();
#pragma unroll
    for (int i = 0; i < 4; i++) {
        int n = n0 + ty + 8 * i;
        float q = tile[tx][ty + 8 * i] * sbi[n];
        int q1 = __float2int_rn(q);
        int q2 = __float2int_rn((q - (float)q1) * 128.0f);
        size_t o = (size_t)n * 1024 + k0 + tx;
        T1[o] = (int8_t)q1;
        T2[o] = (int8_t)q2;
    }
}

// ===========================================================================
// int8 2-digit GEMM: C[M,N] = (sa*(A1+A2/128)) @ (sb*(B1+B2/128))^T (drop A2B2).
// CTA 128x128, 512 threads (16 warps, warp tile 32x32), K=1024, BK=64, 3-stage.
// ===========================================================================
__global__ __launch_bounds__(512, 1) void i8gemm(const int8_t* __restrict__ A1g,
                                                 const int8_t* __restrict__ A2g,
                                                 const float* __restrict__ sa,
                                                 const int8_t* __restrict__ B1g,
                                                 const int8_t* __restrict__ B2g,
                                                 const float* __restrict__ sb,
                                                 float* __restrict__ C, int N) {
    extern __shared__ uint32_t sm[];
    const int t    = threadIdx.x;
    const int wid  = t >> 5;
    const int lane = t & 31;
    const int wm   = wid >> 2;        // 0..3
    const int wn   = wid & 3;         // 0..3
    const int lr   = lane >> 2;       // 0..7
    const int lc   = lane & 3;        // 0..3
    const int bx   = blockIdx.x;
    const int by   = blockIdx.y;

    int acc1[2][4][4], acc2[2][4][4];
#pragma unroll
    for (int mi = 0; mi < 2; mi++)
#pragma unroll
        for (int ni = 0; ni < 4; ni++)
#pragma unroll
            for (int c = 0; c < 4; c++) { acc1[mi][ni][c] = 0; acc2[mi][ni][c] = 0; }

    const int lrow = t >> 2;          // 0..127 loader row
    const int lch  = t & 3;           // 16B chunk

#define LOADK(s, kt)                                                                     \
    {                                                                                    \
        uint32_t* d = sm + (s) * STGW + lrow * LDW + lch * 4;                            \
        const size_t go = (size_t)lrow * 1024 + (kt) * IBK + lch * 16;                   \
        cp16(d,             A1g + (size_t)by * 128 * 1024 + go);                         \
        cp16(d + BUFW,      A2g + (size_t)by * 128 * 1024 + go);                         \
        cp16(d + 2 * BUFW,  B1g + (size_t)bx * 128 * 1024 + go);                         \
        cp16(d + 3 * BUFW,  B2g + (size_t)bx * 128 * 1024 + go);                         \
        asm volatile("cp.async.commit_group;\n" ::: "memory");                           \
    }

    LOADK(0, 0);
    LOADK(1, 1);

    const int NT = 1024 / IBK;        // 16
    for (int kt = 0; kt < NT; kt++) {
        if (kt < NT - 1) asm volatile("cp.async.wait_group 1;\n" ::: "memory");
        else             asm volatile("cp.async.wait_group 0;\n" ::: "memory");
        __syncthreads();

        if (kt + 2 < NT) LOADK((kt + 2) % ISTG, kt + 2);

        const uint32_t* S = sm + (kt % ISTG) * STGW;
        const uint32_t* A1s = S;
        const uint32_t* A2s = S + BUFW;
        const uint32_t* B1s = S + 2 * BUFW;
        const uint32_t* B2s = S + 3 * BUFW;

#pragma unroll
        for (int sub = 0; sub < 2; sub++) {
            uint32_t a1f[2][4], a2f[2][4], b1f[4][2], b2f[4][2];
#pragma unroll
            for (int mi = 0; mi < 2; mi++) {
                const int base = (wm * 32 + mi * 16 + lr) * LDW + sub * 8 + lc;
                a1f[mi][0] = A1s[base];
                a1f[mi][1] = A1s[base + 8 * LDW];
                a1f[mi][2] = A1s[base + 4];
                a1f[mi][3] = A1s[base + 8 * LDW + 4];
                a2f[mi][0] = A2s[base];
                a2f[mi][1] = A2s[base + 8 * LDW];
                a2f[mi][2] = A2s[base + 4];
                a2f[mi][3] = A2s[base + 8 * LDW + 4];
            }
#pragma unroll
            for (int ni = 0; ni < 4; ni++) {
                const int base = (wn * 32 + ni * 8 + lr) * LDW + sub * 8 + lc;
                b1f[ni][0] = B1s[base];
                b1f[ni][1] = B1s[base + 4];
                b2f[ni][0] = B2s[base];
                b2f[ni][1] = B2s[base + 4];
            }
#pragma unroll
            for (int mi = 0; mi < 2; mi++)
#pragma unroll
                for (int ni = 0; ni < 4; ni++) {
                    mma_s8(acc1[mi][ni], a1f[mi], b1f[ni]);
                    mma_s8(acc2[mi][ni], a1f[mi], b2f[ni]);
                    mma_s8(acc2[mi][ni], a2f[mi], b1f[ni]);
                }
        }
    }

    // epilogue: dequantize + store
#pragma unroll
    for (int mi = 0; mi < 2; mi++) {
        const int r0 = by * 128 + wm * 32 + mi * 16 + lr;
        const float s0 = sa[r0], s1 = sa[r0 + 8];
#pragma unroll
        for (int ni = 0; ni < 4; ni++) {
            const int c0 = bx * 128 + wn * 32 + ni * 8 + 2 * lc;
            const float t0 = sb[c0], t1 = sb[c0 + 1];
            float v00 = s0 * t0 * ((float)acc1[mi][ni][0] + (float)acc2[mi][ni][0] * 0.0078125f);
            float v01 = s0 * t1 * ((float)acc1[mi][ni][1] + (float)acc2[mi][ni][1] * 0.0078125f);
            float v10 = s1 * t0 * ((float)acc1[mi][ni][2] + (float)acc2[mi][ni][2] * 0.0078125f);
            float v11 = s1 * t1 * ((float)acc1[mi][ni][3] + (float)acc2[mi][ni][3] * 0.0078125f);
            *(float2*)&C[(size_t)r0 * N + c0]       = make_float2(v00, v01);
            *(float2*)&C[(size_t)(r0 + 8) * N + c0] = make_float2(v10, v11);
        }
    }
#undef LOADK
}

// ===========================================================================
// Tensor-core sliding-window attention (round-4 proven), fp32 ctx out.
// ===========================================================================
__global__ __launch_bounds__(128) void attn_tc(const float* __restrict__ qkv,
                                               float* __restrict__ ctx) {
    extern __shared__ float smf[];
    float* Qs = smf;
    float* Ks = smf + 64 * LQ;
    float* Ps = smf + 2 * 64 * LQ;
    float* Vs = smf + 3 * 64 * LQ;

    const int qb = blockIdx.x;
    const int h  = blockIdx.y;
    const int t  = threadIdx.x;
    const int w  = t >> 5;
    const int lane = t & 31;
    const int lr = lane >> 2;
    const int lc = lane & 3;
    const int q0 = qb * 64;
    const int col0 = h * HD;

#pragma unroll
    for (int i = 0; i < 8; i++) {
        int id = t + 128 * i;
        int r = id >> 4, c4 = (id & 15) << 2;
        float4 v = *(const float4*)&qkv[(size_t)(q0 + r) * QKV_N + col0 + c4];
        v.x = __uint_as_float(f2tf(v.x));
        v.y = __uint_as_float(f2tf(v.y));
        v.z = __uint_as_float(f2tf(v.z));
        v.w = __uint_as_float(f2tf(v.w));
        *(float4*)&Qs[r * LQ + c4] = v;
    }

    float o[8][4];
#pragma unroll
    for (int nt = 0; nt < 8; nt++)
#pragma unroll
        for (int c = 0; c < 4; c++) o[nt][c] = 0.0f;
    float m[2] = {-1e30f, -1e30f};
    float l[2] = {0.0f, 0.0f};

    const int ktlo = (qb >= 4) ? qb - 4 : 0;
    for (int kt = ktlo; kt <= qb; kt++) {
        const int k0 = kt * 64;
        __syncthreads();
#pragma unroll
        for (int i = 0; i < 8; i++) {
            int id = t + 128 * i;
            int r = id >> 4, c4 = (id & 15) << 2;
            float4 kv = *(const float4*)&qkv[(size_t)(k0 + r) * QKV_N + EMB + col0 + c4];
            kv.x = __uint_as_float(f2tf(kv.x));
            kv.y = __uint_as_float(f2tf(kv.y));
            kv.z = __uint_as_float(f2tf(kv.z));
            kv.w = __uint_as_float(f2tf(kv.w));
            *(float4*)&Ks[r * LQ + c4] = kv;
            float4 vv = *(const float4*)&qkv[(size_t)(k0 + r) * QKV_N + 2 * EMB + col0 + c4];
            vv.x = __uint_as_float(f2tf(vv.x));
            vv.y = __uint_as_float(f2tf(vv.y));
            vv.z = __uint_as_float(f2tf(vv.z));
            vv.w = __uint_as_float(f2tf(vv.w));
            *(float4*)&Vs[r * LV + c4] = vv;
        }
        __syncthreads();

        float acc[8][4];
#pragma unroll
        for (int nt = 0; nt < 8; nt++)
#pragma unroll
            for (int c = 0; c < 4; c++) acc[nt][c] = 0.0f;

        const uint32_t* Qu = (const uint32_t*)Qs;
        const uint32_t* Ku = (const uint32_t*)Ks;
#pragma unroll
        for (int ks = 0; ks < 8; ks++) {
            uint32_t af[4];
            const uint32_t* ap = &Qu[(16 * w + lr) * LQ + 8 * ks + lc];
            af[0] = ap[0];
            af[1] = ap[8 * LQ];
            af[2] = ap[4];
            af[3] = ap[8 * LQ + 4];
#pragma unroll
            for (int nt = 0; nt < 8; nt++) {
                uint32_t bf[2];
                const uint32_t* bp = &Ku[(8 * nt + lr) * LQ + 8 * ks + lc];
                bf[0] = bp[0];
                bf[1] = bp[4];
                mma_tf32(acc[nt], af, bf);
            }
        }

#pragma unroll
        for (int i = 0; i < 2; i++) {
            const int qi = q0 + 16 * w + lr + 8 * i;
            float sv[16];
            float mt = -1e30f;
#pragma unroll
            for (int nt = 0; nt < 8; nt++) {
#pragma unroll
                for (int c = 0; c < 2; c++) {
                    int kj = k0 + 8 * nt + 2 * lc + c;
                    bool ok = (kj <= qi) && (kj > qi - WIN);
                    float s = acc[nt][2 * i + c] * 0.125f;
                    sv[nt * 2 + c] = ok ? s : -1e30f;
                    mt = fmaxf(mt, sv[nt * 2 + c]);
                }
            }
            mt = fmaxf(mt, __shfl_xor_sync(0xffffffffu, mt, 1));
            mt = fmaxf(mt, __shfl_xor_sync(0xffffffffu, mt, 2));

            float alpha = 1.0f;
            if (mt > m[i]) { alpha = __expf(m[i] - mt); m[i] = mt; }

            float ls = 0.0f;
            float p[16];
#pragma unroll
            for (int j = 0; j < 16; j++) {
                p[j] = (sv[j] > -1e29f) ? __expf(sv[j] - m[i]) : 0.0f;
                ls += p[j];
            }
            ls += __shfl_xor_sync(0xffffffffu, ls, 1);
            ls += __shfl_xor_sync(0xffffffffu, ls, 2);

            l[i] = l[i] * alpha + ls;
#pragma unroll
            for (int nt = 0; nt < 8; nt++) {
                o[nt][2 * i]     *= alpha;
                o[nt][2 * i + 1] *= alpha;
                float2 pr = make_float2(__uint_as_float(f2tf(p[nt * 2])),
                                        __uint_as_float(f2tf(p[nt * 2 + 1])));
                *(float2*)&Ps[(16 * w + lr + 8 * i) * LQ + 8 * nt + 2 * lc] = pr;
            }
        }
        __syncwarp();

        const uint32_t* Pu = (const uint32_t*)Ps;
        const uint32_t* Vu = (const uint32_t*)Vs;
#pragma unroll
        for (int ks = 0; ks < 8; ks++) {
            uint32_t pa[4];
            const uint32_t* pp = &Pu[(16 * w + lr) * LQ + 8 * ks + lc];
            pa[0] = pp[0];
            pa[1] = pp[8 * LQ];
            pa[2] = pp[4];
            pa[3] = pp[8 * LQ + 4];
#pragma unroll
            for (int nt = 0; nt < 8; nt++) {
                uint32_t vb[2];
                const uint32_t* vp = &Vu[(8 * ks + lc) * LV + 8 * nt + lr];
                vb[0] = vp[0];
                vb[1] = vp[4 * LV];
                mma_tf32(o[nt], pa, vb);
            }
        }
    }

    const float inv0 = 1.0f / l[0];
    const float inv1 = 1.0f / l[1];
    const int row0 = q0 + 16 * w + lr;
#pragma unroll
    for (int nt = 0; nt < 8; nt++) {
        int c0 = col0 + 8 * nt + 2 * lc;
        *(float2*)&ctx[(size_t)row0 * EMB + c0] =
            make_float2(o[nt][0] * inv0, o[nt][1] * inv0);
        *(float2*)&ctx[(size_t)(row0 + 8) * EMB + c0] =
            make_float2(o[nt][2] * inv1, o[nt][3] * inv1);
    }
}

// ===========================================================================
extern "C" void kernel_launch(void* const* d_in, const int* in_sizes, int n_in,
                              void* d_out, int out_size) {
    const float* x     = (const float*)d_in[0];
    const float* w_qkv = (const float*)d_in[2];
    const float* w_out = (const float*)d_in[3];
    float* out = (float*)d_out;

    float *qkv, *ctx, *sax, *sac, *sbq, *sbqi, *sbo, *sboi;
    int8_t *x1, *x2, *c1, *c2, *bq1, *bq2, *bo1, *bo2;
    cudaGetSymbolAddress((void**)&qkv, g_qkv);
    cudaGetSymbolAddress((void**)&ctx, g_ctx);
    cudaGetSymbolAddress((void**)&x1, g_x1);
    cudaGetSymbolAddress((void**)&x2, g_x2);
    cudaGetSymbolAddress((void**)&c1, g_c1);
    cudaGetSymbolAddress((void**)&c2, g_c2);
    cudaGetSymbolAddress((void**)&bq1, g_bq1);
    cudaGetSymbolAddress((void**)&bq2, g_bq2);
    cudaGetSymbolAddress((void**)&bo1, g_bo1);
    cudaGetSymbolAddress((void**)&bo2, g_bo2);
    cudaGetSymbolAddress((void**)&sax, g_sax);
    cudaGetSymbolAddress((void**)&sac, g_sac);
    cudaGetSymbolAddress((void**)&sbq, g_sbq);
    cudaGetSymbolAddress((void**)&sbqi, g_sbqi);
    cudaGetSymbolAddress((void**)&sbo, g_sbo);
    cudaGetSymbolAddress((void**)&sboi, g_sboi);

    cudaFuncSetAttribute(attn_tc, cudaFuncAttributeMaxDynamicSharedMemorySize, ATTN_SMEM);
    cudaFuncSetAttribute(i8gemm, cudaFuncAttributeMaxDynamicSharedMemorySize, I8_SMEM);

    // 0) quantize operands
    quant_rows<<<SEQ, 256>>>(x, x1, x2, sax);
    colmax<<<QKV_N / 32, 256>>>(w_qkv, sbq, sbqi, QKV_N);
    tq<<<dim3(QKV_N / 32, EMB / 32), 256>>>(w_qkv, sbqi, bq1, bq2, QKV_N);
    colmax<<<EMB / 32, 256>>>(w_out, sbo, sboi, EMB);
    tq<<<dim3(EMB / 32, EMB / 32), 256>>>(w_out, sboi, bo1, bo2, EMB);

    // 1) qkv = x @ w_qkv  (int8 2-digit)
    i8gemm<<<dim3(QKV_N / 128, SEQ / 128), 512, I8_SMEM>>>(x1, x2, sax, bq1, bq2, sbq, qkv, QKV_N);

    // 2) attention
    attn_tc<<<dim3(SEQ / 64, NH), 128, ATTN_SMEM>>>(qkv, ctx);

    // 3) out = ctx @ w_out (int8 2-digit)
    quant_rows<<<SEQ, 256>>>(ctx, c1, c2, sac);
    i8gemm<<<dim3(EMB / 128, SEQ / 128), 512, I8_SMEM>>>(c1, c2, sac, bo1, bo2, sbo, out, EMB);
}

// round 8
// speedup vs baseline: 2.9509x; 2.9509x over previous
#include <cuda_runtime.h>
#include <cstdint>

#define SEQ   4096
#define EMB   1024
#define NH    16
#define HD    64
#define WIN   256
#define QKV_N 3072

// ---- GEMM tiling (round-4 proven) ----
#define BM 128
#define BN 128
#define BK 32
#define STG 3
#define LDA 36
#define LDB 136
#define ABUF (BM * LDA)
#define BBUF (BK * LDB)
#define GEMM_SMEM ((STG * ABUF + STG * BBUF) * 4)

// ---- attention tiling: Q, P, double-buffered K/V ----
#define LQ 68
#define LV 72
#define QS_OFF  0
#define PS_OFF  (64 * LQ)
#define KS_OFF  (2 * 64 * LQ)                 // + s * 64*LQ
#define VS_OFF  (4 * 64 * LQ)                 // + s * 64*LV
#define ATTN_F  (4 * 64 * LQ + 2 * 64 * LV)
#define ATTN_SMEM (ATTN_F * 4)

static __device__ float g_qkv[SEQ * QKV_N];    // tf32-rounded q|k|v
static __device__ float g_attn[SEQ * EMB];     // tf32-rounded ctx
static __device__ float g_xr[SEQ * EMB];       // tf32-rounded x
static __device__ float g_wqkvr[EMB * QKV_N];  // tf32-rounded w_qkv
static __device__ float g_woutr[EMB * EMB];    // tf32-rounded w_out

__device__ __forceinline__ uint32_t f2tf(float x) {
    uint32_t r;
    asm("cvt.rna.tf32.f32 %0, %1;" : "=r"(r) : "f"(x));
    return r;
}
__device__ __forceinline__ float tfr(float x) { return __uint_as_float(f2tf(x)); }

__device__ __forceinline__ void mma_tf32(float d[4], const uint32_t a[4], const uint32_t b[2]) {
    asm volatile(
        "mma.sync.aligned.m16n8k8.row.col.f32.tf32.tf32.f32 "
        "{%0,%1,%2,%3}, {%4,%5,%6,%7}, {%8,%9}, {%0,%1,%2,%3};\n"
        : "+f"(d[0]), "+f"(d[1]), "+f"(d[2]), "+f"(d[3])
        : "r"(a[0]), "r"(a[1]), "r"(a[2]), "r"(a[3]), "r"(b[0]), "r"(b[1]));
}
__device__ __forceinline__ void cp16(float* smem_dst, const float* gsrc) {
    uint32_t saddr;
    asm("{ .reg .u64 t; cvta.to.shared.u64 t, %1; cvt.u32.u64 %0, t; }" : "=r"(saddr) : "l"(smem_dst));
    asm volatile("cp.async.cg.shared.global [%0], [%1], 16;\n" :: "r"(saddr), "l"(gsrc) : "memory");
}

// ---------------------------------------------------------------------------
// Elementwise tf32 rounding (rna), vectorized.
// ---------------------------------------------------------------------------
__global__ __launch_bounds__(256) void round_tf32(const float4* __restrict__ src,
                                                  float4* __restrict__ dst, int n4) {
    int i = blockIdx.x * blockDim.x + threadIdx.x;
    if (i < n4) {
        float4 v = src[i];
        v.x = tfr(v.x);
        v.y = tfr(v.y);
        v.z = tfr(v.z);
        v.w = tfr(v.w);
        dst[i] = v;
    }
}

// ---------------------------------------------------------------------------
// tf32 tensor-core GEMM (round-4 proven). RND: round output to tf32.
// ---------------------------------------------------------------------------
template <bool RND>
__global__ __launch_bounds__(256, 2) void tf32gemm(const float* __restrict__ A,
                                                   const float* __restrict__ B,
                                                   float* __restrict__ C,
                                                   int M, int N, int K) {
    extern __shared__ float sm[];
    float* As = sm;
    float* Bs = sm + STG * ABUF;

    const int t    = threadIdx.x;
    const int w    = t >> 5;
    const int lane = t & 31;
    const int wm   = w >> 2;
    const int wn   = w & 3;
    const int lr   = lane >> 2;
    const int lc   = lane & 3;
    const int bx   = blockIdx.x;
    const int by   = blockIdx.y;

    float acc[4][4][4];
#pragma unroll
    for (int i = 0; i < 4; i++)
#pragma unroll
        for (int j = 0; j < 4; j++)
#pragma unroll
            for (int c = 0; c < 4; c++) acc[i][j][c] = 0.0f;

    const int NT = K / BK;

#define LOAD_TILE(stage, ktile)                                                        \
    {                                                                                  \
        float* Ad = As + (stage) * ABUF;                                               \
        float* Bd = Bs + (stage) * BBUF;                                               \
        const int k0 = (ktile) * BK;                                                   \
        _Pragma("unroll")                                                              \
        for (int i = 0; i < 4; i++) {                                                  \
            int id = t + 256 * i;                                                      \
            int r = id >> 3, c4 = (id & 7) << 2;                                       \
            cp16(&Ad[r * LDA + c4], &A[(size_t)(by * BM + r) * K + k0 + c4]);          \
        }                                                                              \
        _Pragma("unroll")                                                              \
        for (int i = 0; i < 4; i++) {                                                  \
            int id = t + 256 * i;                                                      \
            int r = id >> 5, c4 = (id & 31) << 2;                                      \
            cp16(&Bd[r * LDB + c4], &B[(size_t)(k0 + r) * N + bx * BN + c4]);          \
        }                                                                              \
        asm volatile("cp.async.commit_group;\n" ::: "memory");                         \
    }

    LOAD_TILE(0, 0);
    if (NT > 1) LOAD_TILE(1, 1);

    for (int kt = 0; kt < NT; kt++) {
        if (kt + 2 < NT) asm volatile("cp.async.wait_group 1;\n" ::: "memory");
        else             asm volatile("cp.async.wait_group 0;\n" ::: "memory");
        __syncthreads();

        if (kt + 2 < NT) LOAD_TILE((kt + 2) % STG, kt + 2);

        const uint32_t* Ab = (const uint32_t*)(As + (kt % STG) * ABUF);
        const uint32_t* Bb = (const uint32_t*)(Bs + (kt % STG) * BBUF);

#pragma unroll
        for (int ks = 0; ks < 4; ks++) {
            uint32_t af[4][4], bf[4][2];
#pragma unroll
            for (int mi = 0; mi < 4; mi++) {
                const uint32_t* ap = &Ab[(wm * 64 + mi * 16 + lr) * LDA + ks * 8 + lc];
                af[mi][0] = ap[0];
                af[mi][1] = ap[8 * LDA];
                af[mi][2] = ap[4];
                af[mi][3] = ap[8 * LDA + 4];
            }
#pragma unroll
            for (int ni = 0; ni < 4; ni++) {
                const uint32_t* bp = &Bb[(ks * 8 + lc) * LDB + wn * 32 + ni * 8 + lr];
                bf[ni][0] = bp[0];
                bf[ni][1] = bp[4 * LDB];
            }
#pragma unroll
            for (int mi = 0; mi < 4; mi++)
#pragma unroll
                for (int ni = 0; ni < 4; ni++)
                    mma_tf32(acc[mi][ni], af[mi], bf[ni]);
        }
        __syncthreads();
    }

#pragma unroll
    for (int mi = 0; mi < 4; mi++) {
        const int r0 = by * BM + wm * 64 + mi * 16 + lr;
#pragma unroll
        for (int ni = 0; ni < 4; ni++) {
            const int c0 = bx * BN + wn * 32 + ni * 8 + 2 * lc;
            float v0 = acc[mi][ni][0], v1 = acc[mi][ni][1];
            float v2 = acc[mi][ni][2], v3 = acc[mi][ni][3];
            if (RND) { v0 = tfr(v0); v1 = tfr(v1); v2 = tfr(v2); v3 = tfr(v3); }
            *(float2*)&C[(size_t)r0 * N + c0]       = make_float2(v0, v1);
            *(float2*)&C[(size_t)(r0 + 8) * N + c0] = make_float2(v2, v3);
        }
    }
#undef LOAD_TILE
}

// ---------------------------------------------------------------------------
// Tensor-core sliding-window attention with cp.async double-buffered K/V.
// Block = (64-query tile, head), 4 warps. qkv is pre-rounded to tf32.
// ---------------------------------------------------------------------------
__global__ __launch_bounds__(128) void attn_tc(const float* __restrict__ qkv,
                                               float* __restrict__ ctx) {
    extern __shared__ float sm[];
    float* Qs = sm + QS_OFF;
    float* Ps = sm + PS_OFF;

    const int qb = blockIdx.x;
    const int h  = blockIdx.y;
    const int t  = threadIdx.x;
    const int w  = t >> 5;
    const int lane = t & 31;
    const int lr = lane >> 2;
    const int lc = lane & 3;
    const int q0 = qb * 64;
    const int col0 = h * HD;

    // Q tile: plain vector loads (already tf32-rounded)
#pragma unroll
    for (int i = 0; i < 8; i++) {
        int id = t + 128 * i;
        int r = id >> 4, c4 = (id & 15) << 2;
        *(float4*)&Qs[r * LQ + c4] =
            *(const float4*)&qkv[(size_t)(q0 + r) * QKV_N + col0 + c4];
    }

#define LOADKV(s, kt)                                                                   \
    {                                                                                   \
        float* Kd = sm + KS_OFF + (s) * 64 * LQ;                                        \
        float* Vd = sm + VS_OFF + (s) * 64 * LV;                                        \
        const int kk0 = (kt) * 64;                                                      \
        _Pragma("unroll")                                                               \
        for (int i = 0; i < 8; i++) {                                                   \
            int id = t + 128 * i;                                                       \
            int r = id >> 4, c4 = (id & 15) << 2;                                       \
            cp16(&Kd[r * LQ + c4], &qkv[(size_t)(kk0 + r) * QKV_N + EMB + col0 + c4]);  \
            cp16(&Vd[r * LV + c4], &qkv[(size_t)(kk0 + r) * QKV_N + 2 * EMB + col0 + c4]); \
        }                                                                               \
        asm volatile("cp.async.commit_group;\n" ::: "memory");                          \
    }

    float o[8][4];
#pragma unroll
    for (int nt = 0; nt < 8; nt++)
#pragma unroll
        for (int c = 0; c < 4; c++) o[nt][c] = 0.0f;
    float m[2] = {-1e30f, -1e30f};
    float l[2] = {0.0f, 0.0f};

    const int ktlo = (qb >= 4) ? qb - 4 : 0;
    LOADKV(0, ktlo);

    for (int kt = ktlo; kt <= qb; kt++) {
        const int s = (kt - ktlo) & 1;
        const int k0 = kt * 64;

        asm volatile("cp.async.wait_group 0;\n" ::: "memory");
        __syncthreads();                       // buffer s ready; all done with s^1

        if (kt < qb) LOADKV(s ^ 1, kt + 1);    // overlap next load with compute

        const uint32_t* Qu = (const uint32_t*)Qs;
        const uint32_t* Ku = (const uint32_t*)(sm + KS_OFF + s * 64 * LQ);
        const uint32_t* Vu = (const uint32_t*)(sm + VS_OFF + s * 64 * LV);

        // S = Q K^T
        float acc[8][4];
#pragma unroll
        for (int nt = 0; nt < 8; nt++)
#pragma unroll
            for (int c = 0; c < 4; c++) acc[nt][c] = 0.0f;

#pragma unroll
        for (int ks = 0; ks < 8; ks++) {
            uint32_t af[4];
            const uint32_t* ap = &Qu[(16 * w + lr) * LQ + 8 * ks + lc];
            af[0] = ap[0];
            af[1] = ap[8 * LQ];
            af[2] = ap[4];
            af[3] = ap[8 * LQ + 4];
#pragma unroll
            for (int nt = 0; nt < 8; nt++) {
                uint32_t bf[2];
                const uint32_t* bp = &Ku[(8 * nt + lr) * LQ + 8 * ks + lc];
                bf[0] = bp[0];
                bf[1] = bp[4];
                mma_tf32(acc[nt], af, bf);
            }
        }

        // masked online softmax: 2 rows per thread
#pragma unroll
        for (int i = 0; i < 2; i++) {
            const int qi = q0 + 16 * w + lr + 8 * i;
            float sv[16];
            float mt = -1e30f;
#pragma unroll
            for (int nt = 0; nt < 8; nt++) {
#pragma unroll
                for (int c = 0; c < 2; c++) {
                    int kj = k0 + 8 * nt + 2 * lc + c;
                    bool ok = (kj <= qi) && (kj > qi - WIN);
                    float sx = acc[nt][2 * i + c] * 0.125f;
                    sv[nt * 2 + c] = ok ? sx : -1e30f;
                    mt = fmaxf(mt, sv[nt * 2 + c]);
                }
            }
            mt = fmaxf(mt, __shfl_xor_sync(0xffffffffu, mt, 1));
            mt = fmaxf(mt, __shfl_xor_sync(0xffffffffu, mt, 2));

            float alpha = 1.0f;
            if (mt > m[i]) { alpha = __expf(m[i] - mt); m[i] = mt; }

            float ls = 0.0f;
            float p[16];
#pragma unroll
            for (int j = 0; j < 16; j++) {
                p[j] = (sv[j] > -1e29f) ? __expf(sv[j] - m[i]) : 0.0f;
                ls += p[j];
            }
            ls += __shfl_xor_sync(0xffffffffu, ls, 1);
            ls += __shfl_xor_sync(0xffffffffu, ls, 2);

            l[i] = l[i] * alpha + ls;
#pragma unroll
            for (int nt = 0; nt < 8; nt++) {
                o[nt][2 * i]     *= alpha;
                o[nt][2 * i + 1] *= alpha;
                float2 pr = make_float2(tfr(p[nt * 2]), tfr(p[nt * 2 + 1]));
                *(float2*)&Ps[(16 * w + lr + 8 * i) * LQ + 8 * nt + 2 * lc] = pr;
            }
        }
        __syncwarp();

        // O += P V
        const uint32_t* Pu = (const uint32_t*)Ps;
#pragma unroll
        for (int ks = 0; ks < 8; ks++) {
            uint32_t pa[4];
            const uint32_t* pp = &Pu[(16 * w + lr) * LQ + 8 * ks + lc];
            pa[0] = pp[0];
            pa[1] = pp[8 * LQ];
            pa[2] = pp[4];
            pa[3] = pp[8 * LQ + 4];
#pragma unroll
            for (int nt = 0; nt < 8; nt++) {
                uint32_t vb[2];
                const uint32_t* vp = &Vu[(8 * ks + lc) * LV + 8 * nt + lr];
                vb[0] = vp[0];
                vb[1] = vp[4 * LV];
                mma_tf32(o[nt], pa, vb);
            }
        }
        __syncwarp();
    }

    // epilogue: normalize, round to tf32, store (feeds out-proj directly)
    const float inv0 = 1.0f / l[0];
    const float inv1 = 1.0f / l[1];
    const int row0 = q0 + 16 * w + lr;
#pragma unroll
    for (int nt = 0; nt < 8; nt++) {
        int c0 = col0 + 8 * nt + 2 * lc;
        *(float2*)&ctx[(size_t)row0 * EMB + c0] =
            make_float2(tfr(o[nt][0] * inv0), tfr(o[nt][1] * inv0));
        *(float2*)&ctx[(size_t)(row0 + 8) * EMB + c0] =
            make_float2(tfr(o[nt][2] * inv1), tfr(o[nt][3] * inv1));
    }
#undef LOADKV
}

// ---------------------------------------------------------------------------
extern "C" void kernel_launch(void* const* d_in, const int* in_sizes, int n_in,
                              void* d_out, int out_size) {
    const float* x     = (const float*)d_in[0];
    const float* w_qkv = (const float*)d_in[2];
    const float* w_out = (const float*)d_in[3];
    float* out = (float*)d_out;

    float *qkv, *ctx, *xr, *wqkvr, *woutr;
    cudaGetSymbolAddress((void**)&qkv, g_qkv);
    cudaGetSymbolAddress((void**)&ctx, g_attn);
    cudaGetSymbolAddress((void**)&xr, g_xr);
    cudaGetSymbolAddress((void**)&wqkvr, g_wqkvr);
    cudaGetSymbolAddress((void**)&woutr, g_woutr);

    cudaFuncSetAttribute(attn_tc, cudaFuncAttributeMaxDynamicSharedMemorySize, ATTN_SMEM);
    cudaFuncSetAttribute(tf32gemm<true>, cudaFuncAttributeMaxDynamicSharedMemorySize, GEMM_SMEM);
    cudaFuncSetAttribute(tf32gemm<false>, cudaFuncAttributeMaxDynamicSharedMemorySize, GEMM_SMEM);

    // 0) pre-round GEMM operands to tf32
    round_tf32<<<(SEQ * EMB / 4 + 255) / 256, 256>>>((const float4*)x, (float4*)xr, SEQ * EMB / 4);
    round_tf32<<<(EMB * QKV_N / 4 + 255) / 256, 256>>>((const float4*)w_qkv, (float4*)wqkvr, EMB * QKV_N / 4);
    round_tf32<<<(EMB * EMB / 4 + 255) / 256, 256>>>((const float4*)w_out, (float4*)woutr, EMB * EMB / 4);

    // 1) qkv = x @ w_qkv  (epilogue rounds to tf32 for attention)
    tf32gemm<true><<<dim3(QKV_N / BN, SEQ / BM), 256, GEMM_SMEM>>>(xr, wqkvr, qkv, SEQ, QKV_N, EMB);
    // 2) attention (double-buffered K/V)
    attn_tc<<<dim3(SEQ / 64, NH), 128, ATTN_SMEM>>>(qkv, ctx);
    // 3) out = ctx @ w_out
    tf32gemm<false><<<dim3(EMB / BN, SEQ / BM), 256, GEMM_SMEM>>>(ctx, woutr, out, SEQ, EMB, EMB);
}

// round 9
// speedup vs baseline: 3.1857x; 1.0796x over previous
#include <cuda_runtime.h>
#include <cuda_fp16.h>
#include <cstdint>

#define SEQ   4096
#define EMB   1024
#define NH    16
#define HD    64
#define WIN   256
#define QKV_N 3072

// ---- GEMM tiling (round-4 proven) ----
#define BM 128
#define BN 128
#define BK 32
#define STG 3
#define LDA 36
#define LDB 136
#define ABUF (BM * LDA)
#define BBUF (BK * LDB)
#define GEMM_SMEM ((STG * ABUF + STG * BBUF) * 4)

// ---- attention (fp16): Q, P, double-buffered K/V; strides in halves ----
#define LH 72
#define QS_OFF  0
#define PS_OFF  (64 * LH)
#define KS_OFF  (2 * 64 * LH)            // + s * 64*LH
#define VS_OFF  (4 * 64 * LH)            // + s * 64*LH
#define ATTN_SMEM ((6 * 64 * LH) * 2)    // 55296 B

static __device__ __half g_qh[SEQ * EMB];      // Q fp16 [seq][emb]
static __device__ __half g_kh[SEQ * EMB];      // K fp16 [seq][emb]
static __device__ __half g_vt[EMB * SEQ];      // V fp16 transposed: [(h*64+d)][seq]
static __device__ float  g_ctx[SEQ * EMB];     // attention out (tf32-rounded fp32)
static __device__ float  g_xr[SEQ * EMB];      // tf32-rounded x
static __device__ float  g_wqkvr[EMB * QKV_N]; // tf32-rounded w_qkv
static __device__ float  g_woutr[EMB * EMB];   // tf32-rounded w_out

__device__ __forceinline__ uint32_t f2tf(float x) {
    uint32_t r;
    asm("cvt.rna.tf32.f32 %0, %1;" : "=r"(r) : "f"(x));
    return r;
}
__device__ __forceinline__ float tfr(float x) { return __uint_as_float(f2tf(x)); }

__device__ __forceinline__ void mma_tf32(float d[4], const uint32_t a[4], const uint32_t b[2]) {
    asm volatile(
        "mma.sync.aligned.m16n8k8.row.col.f32.tf32.tf32.f32 "
        "{%0,%1,%2,%3}, {%4,%5,%6,%7}, {%8,%9}, {%0,%1,%2,%3};\n"
        : "+f"(d[0]), "+f"(d[1]), "+f"(d[2]), "+f"(d[3])
        : "r"(a[0]), "r"(a[1]), "r"(a[2]), "r"(a[3]), "r"(b[0]), "r"(b[1]));
}
__device__ __forceinline__ void mma_f16(float d[4], const uint32_t a[4], const uint32_t b[2]) {
    asm volatile(
        "mma.sync.aligned.m16n8k16.row.col.f32.f16.f16.f32 "
        "{%0,%1,%2,%3}, {%4,%5,%6,%7}, {%8,%9}, {%0,%1,%2,%3};\n"
        : "+f"(d[0]), "+f"(d[1]), "+f"(d[2]), "+f"(d[3])
        : "r"(a[0]), "r"(a[1]), "r"(a[2]), "r"(a[3]), "r"(b[0]), "r"(b[1]));
}
__device__ __forceinline__ void cp16(const void* smem_dst, const void* gsrc) {
    uint32_t saddr;
    asm("{ .reg .u64 t; cvta.to.shared.u64 t, %1; cvt.u32.u64 %0, t; }" : "=r"(saddr) : "l"(smem_dst));
    asm volatile("cp.async.cg.shared.global [%0], [%1], 16;\n" :: "r"(saddr), "l"(gsrc) : "memory");
}

// ---------------------------------------------------------------------------
__global__ __launch_bounds__(256) void round_tf32(const float4* __restrict__ src,
                                                  float4* __restrict__ dst, int n4) {
    int i = blockIdx.x * blockDim.x + threadIdx.x;
    if (i < n4) {
        float4 v = src[i];
        v.x = tfr(v.x);
        v.y = tfr(v.y);
        v.z = tfr(v.z);
        v.w = tfr(v.w);
        dst[i] = v;
    }
}

// ---------------------------------------------------------------------------
// tf32 tensor-core GEMM (round-4 proven mainloop).
// MODE 0: plain fp32 C store. MODE 1: qkv split epilogue -> fp16 Q,K + V^T.
// ---------------------------------------------------------------------------
template <int MODE>
__global__ __launch_bounds__(256, 2) void tf32gemm(const float* __restrict__ A,
                                                   const float* __restrict__ B,
                                                   float* __restrict__ C,
                                                   __half* __restrict__ qh,
                                                   __half* __restrict__ kh,
                                                   __half* __restrict__ vt,
                                                   int M, int N, int K) {
    extern __shared__ float sm[];
    float* As = sm;
    float* Bs = sm + STG * ABUF;

    const int t    = threadIdx.x;
    const int w    = t >> 5;
    const int lane = t & 31;
    const int wm   = w >> 2;
    const int wn   = w & 3;
    const int lr   = lane >> 2;
    const int lc   = lane & 3;
    const int bx   = blockIdx.x;
    const int by   = blockIdx.y;

    float acc[4][4][4];
#pragma unroll
    for (int i = 0; i < 4; i++)
#pragma unroll
        for (int j = 0; j < 4; j++)
#pragma unroll
            for (int c = 0; c < 4; c++) acc[i][j][c] = 0.0f;

    const int NT = K / BK;

#define LOAD_TILE(stage, ktile)                                                        \
    {                                                                                  \
        float* Ad = As + (stage) * ABUF;                                               \
        float* Bd = Bs + (stage) * BBUF;                                               \
        const int k0 = (ktile) * BK;                                                   \
        _Pragma("unroll")                                                              \
        for (int i = 0; i < 4; i++) {                                                  \
            int id = t + 256 * i;                                                      \
            int r = id >> 3, c4 = (id & 7) << 2;                                       \
            cp16(&Ad[r * LDA + c4], &A[(size_t)(by * BM + r) * K + k0 + c4]);          \
        }                                                                              \
        _Pragma("unroll")                                                              \
        for (int i = 0; i < 4; i++) {                                                  \
            int id = t + 256 * i;                                                      \
            int r = id >> 5, c4 = (id & 31) << 2;                                      \
            cp16(&Bd[r * LDB + c4], &B[(size_t)(k0 + r) * N + bx * BN + c4]);          \
        }                                                                              \
        asm volatile("cp.async.commit_group;\n" ::: "memory");                         \
    }

    LOAD_TILE(0, 0);
    LOAD_TILE(1, 1);

    for (int kt = 0; kt < NT; kt++) {
        if (kt + 2 < NT) asm volatile("cp.async.wait_group 1;\n" ::: "memory");
        else             asm volatile("cp.async.wait_group 0;\n" ::: "memory");
        __syncthreads();

        if (kt + 2 < NT) LOAD_TILE((kt + 2) % STG, kt + 2);

        const uint32_t* Ab = (const uint32_t*)(As + (kt % STG) * ABUF);
        const uint32_t* Bb = (const uint32_t*)(Bs + (kt % STG) * BBUF);

#pragma unroll
        for (int ks = 0; ks < 4; ks++) {
            uint32_t af[4][4], bf[4][2];
#pragma unroll
            for (int mi = 0; mi < 4; mi++) {
                const uint32_t* ap = &Ab[(wm * 64 + mi * 16 + lr) * LDA + ks * 8 + lc];
                af[mi][0] = ap[0];
                af[mi][1] = ap[8 * LDA];
                af[mi][2] = ap[4];
                af[mi][3] = ap[8 * LDA + 4];
            }
#pragma unroll
            for (int ni = 0; ni < 4; ni++) {
                const uint32_t* bp = &Bb[(ks * 8 + lc) * LDB + wn * 32 + ni * 8 + lr];
                bf[ni][0] = bp[0];
                bf[ni][1] = bp[4 * LDB];
            }
#pragma unroll
            for (int mi = 0; mi < 4; mi++)
#pragma unroll
                for (int ni = 0; ni < 4; ni++)
                    mma_tf32(acc[mi][ni], af[mi], bf[ni]);
        }
        __syncthreads();
    }

#pragma unroll
    for (int mi = 0; mi < 4; mi++) {
        const int r0 = by * BM + wm * 64 + mi * 16 + lr;
#pragma unroll
        for (int ni = 0; ni < 4; ni++) {
            const int c0 = bx * BN + wn * 32 + ni * 8 + 2 * lc;
            float v0 = acc[mi][ni][0], v1 = acc[mi][ni][1];
            float v2 = acc[mi][ni][2], v3 = acc[mi][ni][3];
            if (MODE == 0) {
                *(float2*)&C[(size_t)r0 * N + c0]       = make_float2(v0, v1);
                *(float2*)&C[(size_t)(r0 + 8) * N + c0] = make_float2(v2, v3);
            } else {
                if (c0 < EMB) {
                    *(__half2*)&qh[(size_t)r0 * EMB + c0]       = __floats2half2_rn(v0, v1);
                    *(__half2*)&qh[(size_t)(r0 + 8) * EMB + c0] = __floats2half2_rn(v2, v3);
                } else if (c0 < 2 * EMB) {
                    const int cc = c0 - EMB;
                    *(__half2*)&kh[(size_t)r0 * EMB + cc]       = __floats2half2_rn(v0, v1);
                    *(__half2*)&kh[(size_t)(r0 + 8) * EMB + cc] = __floats2half2_rn(v2, v3);
                } else {
                    const int cc = c0 - 2 * EMB;           // (head*64 + dim), dim even
                    const size_t base = (size_t)cc * SEQ;
                    vt[base + r0]           = __float2half_rn(v0);
                    vt[base + SEQ + r0]     = __float2half_rn(v1);
                    vt[base + r0 + 8]       = __float2half_rn(v2);
                    vt[base + SEQ + r0 + 8] = __float2half_rn(v3);
                }
            }
        }
    }
#undef LOAD_TILE
}

// ---------------------------------------------------------------------------
// fp16 tensor-core sliding-window attention. Block = (64-query tile, head),
// 4 warps, cp.async double-buffered K/V, V pre-transposed per head.
// ---------------------------------------------------------------------------
__global__ __launch_bounds__(128) void attn_h(const __half* __restrict__ qh,
                                              const __half* __restrict__ kh,
                                              const __half* __restrict__ vt,
                                              float* __restrict__ ctx) {
    extern __shared__ __half sh[];
    __half* Qs = sh + QS_OFF;
    __half* Ps = sh + PS_OFF;

    const int qb = blockIdx.x;
    const int h  = blockIdx.y;
    const int t  = threadIdx.x;
    const int w  = t >> 5;
    const int lane = t & 31;
    const int lr = lane >> 2;
    const int lc = lane & 3;
    const int q0 = qb * 64;
    const int col0 = h * HD;

#define LOADKV(s, kt)                                                                   \
    {                                                                                   \
        __half* Kd = sh + KS_OFF + (s) * 64 * LH;                                       \
        __half* Vd = sh + VS_OFF + (s) * 64 * LH;                                       \
        const int kk0 = (kt) * 64;                                                      \
        _Pragma("unroll")                                                               \
        for (int i = 0; i < 4; i++) {                                                   \
            int id = t + 128 * i;                                                       \
            int r = id >> 3, c = (id & 7) << 3;                                         \
            cp16(&Kd[r * LH + c], &kh[(size_t)(kk0 + r) * EMB + col0 + c]);             \
            cp16(&Vd[r * LH + c], &vt[(size_t)(col0 + r) * SEQ + kk0 + c]);             \
        }                                                                               \
        asm volatile("cp.async.commit_group;\n" ::: "memory");                          \
    }

    // Q tile load joins the first commit group
#pragma unroll
    for (int i = 0; i < 4; i++) {
        int id = t + 128 * i;
        int r = id >> 3, c = (id & 7) << 3;
        cp16(&Qs[r * LH + c], &qh[(size_t)(q0 + r) * EMB + col0 + c]);
    }

    float o[8][4];
#pragma unroll
    for (int nt = 0; nt < 8; nt++)
#pragma unroll
        for (int c = 0; c < 4; c++) o[nt][c] = 0.0f;
    float m[2] = {-1e30f, -1e30f};
    float l[2] = {0.0f, 0.0f};

    const int ktlo = (qb >= 4) ? qb - 4 : 0;
    LOADKV(0, ktlo);

    for (int kt = ktlo; kt <= qb; kt++) {
        const int s = (kt - ktlo) & 1;
        const int k0 = kt * 64;

        asm volatile("cp.async.wait_group 0;\n" ::: "memory");
        __syncthreads();

        if (kt < qb) LOADKV(s ^ 1, kt + 1);

        const __half* Kc = sh + KS_OFF + s * 64 * LH;
        const __half* Vc = sh + VS_OFF + s * 64 * LH;

        // S = Q K^T  (fp16 mma, K=16 per step)
        float acc[8][4];
#pragma unroll
        for (int nt = 0; nt < 8; nt++)
#pragma unroll
            for (int c = 0; c < 4; c++) acc[nt][c] = 0.0f;

#pragma unroll
        for (int ks = 0; ks < 4; ks++) {
            uint32_t af[4];
            const __half* qp = &Qs[(16 * w + lr) * LH + 16 * ks + 2 * lc];
            af[0] = *(const uint32_t*)qp;
            af[1] = *(const uint32_t*)(qp + 8 * LH);
            af[2] = *(const uint32_t*)(qp + 8);
            af[3] = *(const uint32_t*)(qp + 8 * LH + 8);
#pragma unroll
            for (int nt = 0; nt < 8; nt++) {
                uint32_t bf[2];
                const __half* kp = &Kc[(8 * nt + lr) * LH + 16 * ks + 2 * lc];
                bf[0] = *(const uint32_t*)kp;
                bf[1] = *(const uint32_t*)(kp + 8);
                mma_f16(acc[nt], af, bf);
            }
        }

        // masked online softmax: 2 rows per thread
#pragma unroll
        for (int i = 0; i < 2; i++) {
            const int qi = q0 + 16 * w + lr + 8 * i;
            float sv[16];
            float mt = -1e30f;
#pragma unroll
            for (int nt = 0; nt < 8; nt++) {
#pragma unroll
                for (int c = 0; c < 2; c++) {
                    int kj = k0 + 8 * nt + 2 * lc + c;
                    bool ok = (kj <= qi) && (kj > qi - WIN);
                    float sx = acc[nt][2 * i + c] * 0.125f;
                    sv[nt * 2 + c] = ok ? sx : -1e30f;
                    mt = fmaxf(mt, sv[nt * 2 + c]);
                }
            }
            mt = fmaxf(mt, __shfl_xor_sync(0xffffffffu, mt, 1));
            mt = fmaxf(mt, __shfl_xor_sync(0xffffffffu, mt, 2));

            float alpha = 1.0f;
            if (mt > m[i]) { alpha = __expf(m[i] - mt); m[i] = mt; }

            float ls = 0.0f;
            float p[16];
#pragma unroll
            for (int j = 0; j < 16; j++) {
                p[j] = (sv[j] > -1e29f) ? __expf(sv[j] - m[i]) : 0.0f;
                ls += p[j];
            }
            ls += __shfl_xor_sync(0xffffffffu, ls, 1);
            ls += __shfl_xor_sync(0xffffffffu, ls, 2);

            l[i] = l[i] * alpha + ls;
#pragma unroll
            for (int nt = 0; nt < 8; nt++) {
                o[nt][2 * i]     *= alpha;
                o[nt][2 * i + 1] *= alpha;
                *(__half2*)&Ps[(16 * w + lr + 8 * i) * LH + 8 * nt + 2 * lc] =
                    __floats2half2_rn(p[nt * 2], p[nt * 2 + 1]);
            }
        }
        __syncwarp();

        // O += P V  (fp16 mma; V transposed in smem: [dim][key])
#pragma unroll
        for (int ks = 0; ks < 4; ks++) {
            uint32_t pa[4];
            const __half* pp = &Ps[(16 * w + lr) * LH + 16 * ks + 2 * lc];
            pa[0] = *(const uint32_t*)pp;
            pa[1] = *(const uint32_t*)(pp + 8 * LH);
            pa[2] = *(const uint32_t*)(pp + 8);
            pa[3] = *(const uint32_t*)(pp + 8 * LH + 8);
#pragma unroll
            for (int nt = 0; nt < 8; nt++) {
                uint32_t vb[2];
                const __half* vp = &Vc[(8 * nt + lr) * LH + 16 * ks + 2 * lc];
                vb[0] = *(const uint32_t*)vp;
                vb[1] = *(const uint32_t*)(vp + 8);
                mma_f16(o[nt], pa, vb);
            }
        }
        __syncwarp();
    }

    // epilogue: normalize, round to tf32, store fp32 ctx (feeds out-proj)
    const float inv0 = 1.0f / l[0];
    const float inv1 = 1.0f / l[1];
    const int row0 = q0 + 16 * w + lr;
#pragma unroll
    for (int nt = 0; nt < 8; nt++) {
        int c0 = col0 + 8 * nt + 2 * lc;
        *(float2*)&ctx[(size_t)row0 * EMB + c0] =
            make_float2(tfr(o[nt][0] * inv0), tfr(o[nt][1] * inv0));
        *(float2*)&ctx[(size_t)(row0 + 8) * EMB + c0] =
            make_float2(tfr(o[nt][2] * inv1), tfr(o[nt][3] * inv1));
    }
#undef LOADKV
}

// ---------------------------------------------------------------------------
extern "C" void kernel_launch(void* const* d_in, const int* in_sizes, int n_in,
                              void* d_out, int out_size) {
    const float* x     = (const float*)d_in[0];
    const float* w_qkv = (const float*)d_in[2];
    const float* w_out = (const float*)d_in[3];
    float* out = (float*)d_out;

    float *ctx, *xr, *wqkvr, *woutr;
    __half *qhp, *khp, *vtp;
    cudaGetSymbolAddress((void**)&ctx, g_ctx);
    cudaGetSymbolAddress((void**)&xr, g_xr);
    cudaGetSymbolAddress((void**)&wqkvr, g_wqkvr);
    cudaGetSymbolAddress((void**)&woutr, g_woutr);
    cudaGetSymbolAddress((void**)&qhp, g_qh);
    cudaGetSymbolAddress((void**)&khp, g_kh);
    cudaGetSymbolAddress((void**)&vtp, g_vt);

    cudaFuncSetAttribute(attn_h, cudaFuncAttributeMaxDynamicSharedMemorySize, ATTN_SMEM);
    cudaFuncSetAttribute(tf32gemm<0>, cudaFuncAttributeMaxDynamicSharedMemorySize, GEMM_SMEM);
    cudaFuncSetAttribute(tf32gemm<1>, cudaFuncAttributeMaxDynamicSharedMemorySize, GEMM_SMEM);

    // 0) pre-round GEMM operands to tf32
    round_tf32<<<(SEQ * EMB / 4 + 255) / 256, 256>>>((const float4*)x, (float4*)xr, SEQ * EMB / 4);
    round_tf32<<<(EMB * QKV_N / 4 + 255) / 256, 256>>>((const float4*)w_qkv, (float4*)wqkvr, EMB * QKV_N / 4);
    round_tf32<<<(EMB * EMB / 4 + 255) / 256, 256>>>((const float4*)w_out, (float4*)woutr, EMB * EMB / 4);

    // 1) qkv = x @ w_qkv -> fp16 Q,K + transposed fp16 V
    tf32gemm<1><<<dim3(QKV_N / BN, SEQ / BM), 256, GEMM_SMEM>>>(
        xr, wqkvr, nullptr, qhp, khp, vtp, SEQ, QKV_N, EMB);
    // 2) attention (fp16 mma)
    attn_h<<<dim3(SEQ / 64, NH), 128, ATTN_SMEM>>>(qhp, khp, vtp, ctx);
    // 3) out = ctx @ w_out
    tf32gemm<0><<<dim3(EMB / BN, SEQ / BM), 256, GEMM_SMEM>>>(
        ctx, woutr, out, nullptr, nullptr, nullptr, SEQ, EMB, EMB);
}

// round 10
// speedup vs baseline: 5.3572x; 1.6817x over previous
#include <cuda_runtime.h>
#include <cuda_fp16.h>
#include <cstdint>

#define SEQ   4096
#define EMB   1024
#define NH    16
#define HD    64
#define WIN   256
#define QKV_N 3072

// ---- fp16 GEMM tiling: 128x128x64, 8 warps (2x4), warp tile 64x32 ----
#define BM 128
#define BN 128
#define BK 64
#define STG 3
#define LHW 72                               // halves per smem row (64 + 8 pad)
#define TILE_H (128 * LHW)                   // halves per matrix tile
#define STAGE_H (2 * TILE_H)                 // A + B
#define GEMM_SMEM (STG * STAGE_H * 2)        // bytes (110592)

// ---- attention (fp16, round-9 proven): strides in halves ----
#define LH 72
#define QS_OFF  0
#define PS_OFF  (64 * LH)
#define KS_OFF  (2 * 64 * LH)
#define VS_OFF  (4 * 64 * LH)
#define ATTN_SMEM ((6 * 64 * LH) * 2)

static __device__ __half g_ah[SEQ * EMB];      // x fp16 [seq][emb]
static __device__ __half g_wqt[QKV_N * EMB];   // w_qkv^T fp16 [N][K]
static __device__ __half g_wot[EMB * EMB];     // w_out^T fp16 [N][K]
static __device__ __half g_qh[SEQ * EMB];      // Q fp16
static __device__ __half g_kh[SEQ * EMB];      // K fp16
static __device__ __half g_vt[EMB * SEQ];      // V fp16 transposed [(h*64+d)][seq]
static __device__ __half g_ch[SEQ * EMB];      // ctx fp16 (GEMM2 A operand)

__device__ __forceinline__ void mma_f16(float d[4], const uint32_t a[4], const uint32_t b[2]) {
    asm volatile(
        "mma.sync.aligned.m16n8k16.row.col.f32.f16.f16.f32 "
        "{%0,%1,%2,%3}, {%4,%5,%6,%7}, {%8,%9}, {%0,%1,%2,%3};\n"
        : "+f"(d[0]), "+f"(d[1]), "+f"(d[2]), "+f"(d[3])
        : "r"(a[0]), "r"(a[1]), "r"(a[2]), "r"(a[3]), "r"(b[0]), "r"(b[1]));
}
__device__ __forceinline__ void cp16(const void* smem_dst, const void* gsrc) {
    uint32_t saddr;
    asm("{ .reg .u64 t; cvta.to.shared.u64 t, %1; cvt.u32.u64 %0, t; }" : "=r"(saddr) : "l"(smem_dst));
    asm volatile("cp.async.cg.shared.global [%0], [%1], 16;\n" :: "r"(saddr), "l"(gsrc) : "memory");
}

// ---------------------------------------------------------------------------
// fp32 -> fp16 elementwise convert
// ---------------------------------------------------------------------------
__global__ __launch_bounds__(256) void to_half(const float4* __restrict__ src,
                                               __half2* __restrict__ dst, int n4) {
    int i = blockIdx.x * blockDim.x + threadIdx.x;
    if (i < n4) {
        float4 v = src[i];
        dst[2 * i]     = __floats2half2_rn(v.x, v.y);
        dst[2 * i + 1] = __floats2half2_rn(v.z, v.w);
    }
}

// ---------------------------------------------------------------------------
// W[K][N] fp32 -> Wt[N][K] fp16
// ---------------------------------------------------------------------------
__global__ __launch_bounds__(256) void transpose_half(const float* __restrict__ W,
                                                      __half* __restrict__ T,
                                                      int K, int N) {
    __shared__ float tile[32][33];
    const int tx = threadIdx.x & 31, ty = threadIdx.x >> 5;
    const int n0 = blockIdx.x * 32, k0 = blockIdx.y * 32;
#pragma unroll
    for (int i = 0; i < 4; i++)
        tile[ty + 8 * i][tx] = W[(size_t)(k0 + ty + 8 * i) * N + n0 + tx];
    __syncthreads();
#pragma unroll
    for (int i = 0; i < 4; i++)
        T[(size_t)(n0 + ty + 8 * i) * K + k0 + tx] = __float2half_rn(tile[tx][ty + 8 * i]);
}

// ---------------------------------------------------------------------------
// fp16 tensor-core GEMM: C[M,N] = A[M,K] @ Bt[N,K]^T, fp32 accumulate.
// 128x128x64 tile, 256 threads, 3-stage cp.async.
// MODE 0: fp32 C store. MODE 1: qkv split epilogue -> fp16 Q,K + V^T.
// ---------------------------------------------------------------------------
template <int MODE>
__global__ __launch_bounds__(256, 2) void hgemm(const __half* __restrict__ A,
                                                const __half* __restrict__ Bt,
                                                float* __restrict__ C,
                                                __half* __restrict__ qh,
                                                __half* __restrict__ kh,
                                                __half* __restrict__ vt,
                                                int M, int N, int K) {
    extern __shared__ __half smh[];

    const int t    = threadIdx.x;
    const int w    = t >> 5;
    const int lane = t & 31;
    const int wm   = w >> 2;
    const int wn   = w & 3;
    const int lr   = lane >> 2;
    const int lc   = lane & 3;
    const int bx   = blockIdx.x;
    const int by   = blockIdx.y;

    float acc[4][4][4];
#pragma unroll
    for (int i = 0; i < 4; i++)
#pragma unroll
        for (int j = 0; j < 4; j++)
#pragma unroll
            for (int c = 0; c < 4; c++) acc[i][j][c] = 0.0f;

    const int NT = K / BK;

    const int ldr = t >> 3;              // 0..31 -> x4 rows of 128
    const int ldc = (t & 7) * 8;         // half offset of 16B chunk

#define LOAD_TILE(stage, ktile)                                                         \
    {                                                                                   \
        __half* Ad = smh + (stage) * STAGE_H;                                           \
        __half* Bd = Ad + TILE_H;                                                       \
        const int k0 = (ktile) * BK;                                                    \
        _Pragma("unroll")                                                               \
        for (int i = 0; i < 4; i++) {                                                   \
            int r = ldr + 32 * i;                                                       \
            cp16(&Ad[r * LHW + ldc], &A[(size_t)(by * BM + r) * K + k0 + ldc]);         \
            cp16(&Bd[r * LHW + ldc], &Bt[(size_t)(bx * BN + r) * K + k0 + ldc]);        \
        }                                                                               \
        asm volatile("cp.async.commit_group;\n" ::: "memory");                          \
    }

    LOAD_TILE(0, 0);
    LOAD_TILE(1, 1);

    for (int kt = 0; kt < NT; kt++) {
        if (kt + 2 < NT) asm volatile("cp.async.wait_group 1;\n" ::: "memory");
        else             asm volatile("cp.async.wait_group 0;\n" ::: "memory");
        __syncthreads();

        if (kt + 2 < NT) LOAD_TILE((kt + 2) % STG, kt + 2);

        const __half* Asm = smh + (kt % STG) * STAGE_H;
        const __half* Bsm = Asm + TILE_H;

#pragma unroll
        for (int ks = 0; ks < 4; ks++) {
            uint32_t af[4][4], bf[4][2];
#pragma unroll
            for (int mi = 0; mi < 4; mi++) {
                const __half* ap = &Asm[(wm * 64 + mi * 16 + lr) * LHW + ks * 16 + 2 * lc];
                af[mi][0] = *(const uint32_t*)ap;
                af[mi][1] = *(const uint32_t*)(ap + 8 * LHW);
                af[mi][2] = *(const uint32_t*)(ap + 8);
                af[mi][3] = *(const uint32_t*)(ap + 8 * LHW + 8);
            }
#pragma unroll
            for (int ni = 0; ni < 4; ni++) {
                const __half* bp = &Bsm[(wn * 32 + ni * 8 + lr) * LHW + ks * 16 + 2 * lc];
                bf[ni][0] = *(const uint32_t*)bp;
                bf[ni][1] = *(const uint32_t*)(bp + 8);
            }
#pragma unroll
            for (int mi = 0; mi < 4; mi++)
#pragma unroll
                for (int ni = 0; ni < 4; ni++)
                    mma_f16(acc[mi][ni], af[mi], bf[ni]);
        }
        __syncthreads();
    }

#pragma unroll
    for (int mi = 0; mi < 4; mi++) {
        const int r0 = by * BM + wm * 64 + mi * 16 + lr;
#pragma unroll
        for (int ni = 0; ni < 4; ni++) {
            const int c0 = bx * BN + wn * 32 + ni * 8 + 2 * lc;
            float v0 = acc[mi][ni][0], v1 = acc[mi][ni][1];
            float v2 = acc[mi][ni][2], v3 = acc[mi][ni][3];
            if (MODE == 0) {
                *(float2*)&C[(size_t)r0 * N + c0]       = make_float2(v0, v1);
                *(float2*)&C[(size_t)(r0 + 8) * N + c0] = make_float2(v2, v3);
            } else {
                if (c0 < EMB) {
                    *(__half2*)&qh[(size_t)r0 * EMB + c0]       = __floats2half2_rn(v0, v1);
                    *(__half2*)&qh[(size_t)(r0 + 8) * EMB + c0] = __floats2half2_rn(v2, v3);
                } else if (c0 < 2 * EMB) {
                    const int cc = c0 - EMB;
                    *(__half2*)&kh[(size_t)r0 * EMB + cc]       = __floats2half2_rn(v0, v1);
                    *(__half2*)&kh[(size_t)(r0 + 8) * EMB + cc] = __floats2half2_rn(v2, v3);
                } else {
                    const int cc = c0 - 2 * EMB;           // head*64 + dim (even)
                    const size_t base = (size_t)cc * SEQ;
                    vt[base + r0]           = __float2half_rn(v0);
                    vt[base + SEQ + r0]     = __float2half_rn(v1);
                    vt[base + r0 + 8]       = __float2half_rn(v2);
                    vt[base + SEQ + r0 + 8] = __float2half_rn(v3);
                }
            }
        }
    }
#undef LOAD_TILE
}

// ---------------------------------------------------------------------------
// fp16 tensor-core sliding-window attention (round-9 proven).
// Epilogue writes fp16 ctx (feeds GEMM2 directly).
// ---------------------------------------------------------------------------
__global__ __launch_bounds__(128) void attn_h(const __half* __restrict__ qh,
                                              const __half* __restrict__ kh,
                                              const __half* __restrict__ vt,
                                              __half* __restrict__ ctx) {
    extern __shared__ __half sh[];
    __half* Qs = sh + QS_OFF;
    __half* Ps = sh + PS_OFF;

    const int qb = blockIdx.x;
    const int h  = blockIdx.y;
    const int t  = threadIdx.x;
    const int w  = t >> 5;
    const int lane = t & 31;
    const int lr = lane >> 2;
    const int lc = lane & 3;
    const int q0 = qb * 64;
    const int col0 = h * HD;

#define LOADKV(s, kt)                                                                   \
    {                                                                                   \
        __half* Kd = sh + KS_OFF + (s) * 64 * LH;                                       \
        __half* Vd = sh + VS_OFF + (s) * 64 * LH;                                       \
        const int kk0 = (kt) * 64;                                                      \
        _Pragma("unroll")                                                               \
        for (int i = 0; i < 4; i++) {                                                   \
            int id = t + 128 * i;                                                       \
            int r = id >> 3, c = (id & 7) << 3;                                         \
            cp16(&Kd[r * LH + c], &kh[(size_t)(kk0 + r) * EMB + col0 + c]);             \
            cp16(&Vd[r * LH + c], &vt[(size_t)(col0 + r) * SEQ + kk0 + c]);             \
        }                                                                               \
        asm volatile("cp.async.commit_group;\n" ::: "memory");                          \
    }

#pragma unroll
    for (int i = 0; i < 4; i++) {
        int id = t + 128 * i;
        int r = id >> 3, c = (id & 7) << 3;
        cp16(&Qs[r * LH + c], &qh[(size_t)(q0 + r) * EMB + col0 + c]);
    }

    float o[8][4];
#pragma unroll
    for (int nt = 0; nt < 8; nt++)
#pragma unroll
        for (int c = 0; c < 4; c++) o[nt][c] = 0.0f;
    float m[2] = {-1e30f, -1e30f};
    float l[2] = {0.0f, 0.0f};

    const int ktlo = (qb >= 4) ? qb - 4 : 0;
    LOADKV(0, ktlo);

    for (int kt = ktlo; kt <= qb; kt++) {
        const int s = (kt - ktlo) & 1;
        const int k0 = kt * 64;

        asm volatile("cp.async.wait_group 0;\n" ::: "memory");
        __syncthreads();

        if (kt < qb) LOADKV(s ^ 1, kt + 1);

        const __half* Kc = sh + KS_OFF + s * 64 * LH;
        const __half* Vc = sh + VS_OFF + s * 64 * LH;

        float acc[8][4];
#pragma unroll
        for (int nt = 0; nt < 8; nt++)
#pragma unroll
            for (int c = 0; c < 4; c++) acc[nt][c] = 0.0f;

#pragma unroll
        for (int ks = 0; ks < 4; ks++) {
            uint32_t af[4];
            const __half* qp = &Qs[(16 * w + lr) * LH + 16 * ks + 2 * lc];
            af[0] = *(const uint32_t*)qp;
            af[1] = *(const uint32_t*)(qp + 8 * LH);
            af[2] = *(const uint32_t*)(qp + 8);
            af[3] = *(const uint32_t*)(qp + 8 * LH + 8);
#pragma unroll
            for (int nt = 0; nt < 8; nt++) {
                uint32_t bf[2];
                const __half* kp = &Kc[(8 * nt + lr) * LH + 16 * ks + 2 * lc];
                bf[0] = *(const uint32_t*)kp;
                bf[1] = *(const uint32_t*)(kp + 8);
                mma_f16(acc[nt], af, bf);
            }
        }

#pragma unroll
        for (int i = 0; i < 2; i++) {
            const int qi = q0 + 16 * w + lr + 8 * i;
            float sv[16];
            float mt = -1e30f;
#pragma unroll
            for (int nt = 0; nt < 8; nt++) {
#pragma unroll
                for (int c = 0; c < 2; c++) {
                    int kj = k0 + 8 * nt + 2 * lc + c;
                    bool ok = (kj <= qi) && (kj > qi - WIN);
                    float sx = acc[nt][2 * i + c] * 0.125f;
                    sv[nt * 2 + c] = ok ? sx : -1e30f;
                    mt = fmaxf(mt, sv[nt * 2 + c]);
                }
            }
            mt = fmaxf(mt, __shfl_xor_sync(0xffffffffu, mt, 1));
            mt = fmaxf(mt, __shfl_xor_sync(0xffffffffu, mt, 2));

            float alpha = 1.0f;
            if (mt > m[i]) { alpha = __expf(m[i] - mt); m[i] = mt; }

            float ls = 0.0f;
            float p[16];
#pragma unroll
            for (int j = 0; j < 16; j++) {
                p[j] = (sv[j] > -1e29f) ? __expf(sv[j] - m[i]) : 0.0f;
                ls += p[j];
            }
            ls += __shfl_xor_sync(0xffffffffu, ls, 1);
            ls += __shfl_xor_sync(0xffffffffu, ls, 2);

            l[i] = l[i] * alpha + ls;
#pragma unroll
            for (int nt = 0; nt < 8; nt++) {
                o[nt][2 * i]     *= alpha;
                o[nt][2 * i + 1] *= alpha;
                *(__half2*)&Ps[(16 * w + lr + 8 * i) * LH + 8 * nt + 2 * lc] =
                    __floats2half2_rn(p[nt * 2], p[nt * 2 + 1]);
            }
        }
        __syncwarp();

#pragma unroll
        for (int ks = 0; ks < 4; ks++) {
            uint32_t pa[4];
            const __half* pp = &Ps[(16 * w + lr) * LH + 16 * ks + 2 * lc];
            pa[0] = *(const uint32_t*)pp;
            pa[1] = *(const uint32_t*)(pp + 8 * LH);
            pa[2] = *(const uint32_t*)(pp + 8);
            pa[3] = *(const uint32_t*)(pp + 8 * LH + 8);
#pragma unroll
            for (int nt = 0; nt < 8; nt++) {
                uint32_t vb[2];
                const __half* vp = &Vc[(8 * nt + lr) * LH + 16 * ks + 2 * lc];
                vb[0] = *(const uint32_t*)vp;
                vb[1] = *(const uint32_t*)(vp + 8);
                mma_f16(o[nt], pa, vb);
            }
        }
        __syncwarp();
    }

    // epilogue: normalize, fp16 ctx
    const float inv0 = 1.0f / l[0];
    const float inv1 = 1.0f / l[1];
    const int row0 = q0 + 16 * w + lr;
#pragma unroll
    for (int nt = 0; nt < 8; nt++) {
        int c0 = col0 + 8 * nt + 2 * lc;
        *(__half2*)&ctx[(size_t)row0 * EMB + c0] =
            __floats2half2_rn(o[nt][0] * inv0, o[nt][1] * inv0);
        *(__half2*)&ctx[(size_t)(row0 + 8) * EMB + c0] =
            __floats2half2_rn(o[nt][2] * inv1, o[nt][3] * inv1);
    }
#undef LOADKV
}

// ---------------------------------------------------------------------------
extern "C" void kernel_launch(void* const* d_in, const int* in_sizes, int n_in,
                              void* d_out, int out_size) {
    const float* x     = (const float*)d_in[0];
    const float* w_qkv = (const float*)d_in[2];
    const float* w_out = (const float*)d_in[3];
    float* out = (float*)d_out;

    __half *ah, *wqt, *wot, *qhp, *khp, *vtp, *chp;
    cudaGetSymbolAddress((void**)&ah, g_ah);
    cudaGetSymbolAddress((void**)&wqt, g_wqt);
    cudaGetSymbolAddress((void**)&wot, g_wot);
    cudaGetSymbolAddress((void**)&qhp, g_qh);
    cudaGetSymbolAddress((void**)&khp, g_kh);
    cudaGetSymbolAddress((void**)&vtp, g_vt);
    cudaGetSymbolAddress((void**)&chp, g_ch);

    cudaFuncSetAttribute(attn_h, cudaFuncAttributeMaxDynamicSharedMemorySize, ATTN_SMEM);
    cudaFuncSetAttribute(hgemm<0>, cudaFuncAttributeMaxDynamicSharedMemorySize, GEMM_SMEM);
    cudaFuncSetAttribute(hgemm<1>, cudaFuncAttributeMaxDynamicSharedMemorySize, GEMM_SMEM);

    // 0) prep: x -> fp16; weights -> transposed fp16
    to_half<<<(SEQ * EMB / 4 + 255) / 256, 256>>>((const float4*)x, (__half2*)ah, SEQ * EMB / 4);
    transpose_half<<<dim3(QKV_N / 32, EMB / 32), 256>>>(w_qkv, wqt, EMB, QKV_N);
    transpose_half<<<dim3(EMB / 32, EMB / 32), 256>>>(w_out, wot, EMB, EMB);

    // 1) qkv = x @ w_qkv -> fp16 Q,K + transposed fp16 V
    hgemm<1><<<dim3(QKV_N / BN, SEQ / BM), 256, GEMM_SMEM>>>(
        ah, wqt, nullptr, qhp, khp, vtp, SEQ, QKV_N, EMB);
    // 2) attention (fp16) -> fp16 ctx
    attn_h<<<dim3(SEQ / 64, NH), 128, ATTN_SMEM>>>(qhp, khp, vtp, chp);
    // 3) out = ctx @ w_out (fp32 store)
    hgemm<0><<<dim3(EMB / BN, SEQ / BM), 256, GEMM_SMEM>>>(
        chp, wot, out, nullptr, nullptr, nullptr, SEQ, EMB, EMB);
}

// round 11
// speedup vs baseline: 5.8068x; 1.0839x over previous
#include <cuda_runtime.h>
#include <cuda_fp16.h>
#include <cstdint>

#define SEQ   4096
#define EMB   1024
#define NH    16
#define HD    64
#define WIN   256
#define QKV_N 3072

// ---- fp16 GEMM tiling: 128x128x64, 8 warps (2x4), warp tile 64x32 ----
#define BM 128
#define BN 128
#define BK 64
#define STG 3
#define LHW 72                               // halves per smem row (64 + 8 pad)
#define TILE_H (128 * LHW)
#define STAGE_H (2 * TILE_H)
#define GEMM_SMEM (STG * STAGE_H * 2)

// ---- attention (fp16): strides in halves ----
#define LH 72
#define QS_OFF  0
#define PS_OFF  (64 * LH)
#define KS_OFF  (2 * 64 * LH)
#define VS_OFF  (4 * 64 * LH)
#define ATTN_SMEM ((6 * 64 * LH) * 2)

static __device__ __half g_ah[SEQ * EMB];      // x fp16 [seq][emb]
static __device__ __half g_wqt[QKV_N * EMB];   // w_qkv^T fp16 [N][K]
static __device__ __half g_wot[EMB * EMB];     // w_out^T fp16 [N][K]
static __device__ __half g_qh[SEQ * EMB];      // Q fp16
static __device__ __half g_kh[SEQ * EMB];      // K fp16
static __device__ __half g_vt[EMB * SEQ];      // V fp16 transposed [(h*64+d)][seq]
static __device__ __half g_ch[SEQ * EMB];      // ctx fp16

__device__ __forceinline__ uint32_t smem_u32(const void* p) {
    uint32_t a;
    asm("{ .reg .u64 t; cvta.to.shared.u64 t, %1; cvt.u32.u64 %0, t; }" : "=r"(a) : "l"(p));
    return a;
}
__device__ __forceinline__ void mma_f16(float d[4], const uint32_t a[4], const uint32_t b[2]) {
    asm volatile(
        "mma.sync.aligned.m16n8k16.row.col.f32.f16.f16.f32 "
        "{%0,%1,%2,%3}, {%4,%5,%6,%7}, {%8,%9}, {%0,%1,%2,%3};\n"
        : "+f"(d[0]), "+f"(d[1]), "+f"(d[2]), "+f"(d[3])
        : "r"(a[0]), "r"(a[1]), "r"(a[2]), "r"(a[3]), "r"(b[0]), "r"(b[1]));
}
__device__ __forceinline__ void ldsm4(uint32_t r[4], uint32_t addr) {
    asm volatile("ldmatrix.sync.aligned.m8n8.x4.shared.b16 {%0,%1,%2,%3}, [%4];"
                 : "=r"(r[0]), "=r"(r[1]), "=r"(r[2]), "=r"(r[3]) : "r"(addr));
}
__device__ __forceinline__ void cp16(const void* smem_dst, const void* gsrc) {
    uint32_t saddr = smem_u32(smem_dst);
    asm volatile("cp.async.cg.shared.global [%0], [%1], 16;\n" :: "r"(saddr), "l"(gsrc) : "memory");
}

// ---------------------------------------------------------------------------
__global__ __launch_bounds__(256) void to_half(const float4* __restrict__ src,
                                               __half2* __restrict__ dst, int n4) {
    int i = blockIdx.x * blockDim.x + threadIdx.x;
    if (i < n4) {
        float4 v = src[i];
        dst[2 * i]     = __floats2half2_rn(v.x, v.y);
        dst[2 * i + 1] = __floats2half2_rn(v.z, v.w);
    }
}

__global__ __launch_bounds__(256) void transpose_half(const float* __restrict__ W,
                                                      __half* __restrict__ T,
                                                      int K, int N) {
    __shared__ float tile[32][33];
    const int tx = threadIdx.x & 31, ty = threadIdx.x >> 5;
    const int n0 = blockIdx.x * 32, k0 = blockIdx.y * 32;
#pragma unroll
    for (int i = 0; i < 4; i++)
        tile[ty + 8 * i][tx] = W[(size_t)(k0 + ty + 8 * i) * N + n0 + tx];
    __syncthreads();
#pragma unroll
    for (int i = 0; i < 4; i++)
        T[(size_t)(n0 + ty + 8 * i) * K + k0 + tx] = __float2half_rn(tile[tx][ty + 8 * i]);
}

// ---------------------------------------------------------------------------
// fp16 tensor-core GEMM with ldmatrix fragment loads.
// MODE 0: fp32 C store. MODE 1: qkv split epilogue -> fp16 Q,K + V^T.
// ---------------------------------------------------------------------------
template <int MODE>
__global__ __launch_bounds__(256, 2) void hgemm(const __half* __restrict__ A,
                                                const __half* __restrict__ Bt,
                                                float* __restrict__ C,
                                                __half* __restrict__ qh,
                                                __half* __restrict__ kh,
                                                __half* __restrict__ vt,
                                                int M, int N, int K) {
    extern __shared__ __half smh[];
    const uint32_t sb = smem_u32(smh);

    const int t    = threadIdx.x;
    const int w    = t >> 5;
    const int lane = t & 31;
    const int wm   = w >> 2;
    const int wn   = w & 3;
    const int lr   = lane >> 2;
    const int lc   = lane & 3;
    const int bx   = blockIdx.x;
    const int by   = blockIdx.y;

    // ldmatrix lane-address components
    const int l15  = lane & 15;
    const int lhi8 = (lane >> 4) * 8;          // A col-half select
    const int brow = ((lane >> 4) << 3) + (lane & 7);
    const int bk8  = ((lane >> 3) & 1) * 8;

    float acc[4][4][4];
#pragma unroll
    for (int i = 0; i < 4; i++)
#pragma unroll
        for (int j = 0; j < 4; j++)
#pragma unroll
            for (int c = 0; c < 4; c++) acc[i][j][c] = 0.0f;

    const int NT = K / BK;
    const int ldr = t >> 3;
    const int ldc = (t & 7) * 8;

#define LOAD_TILE(stage, ktile)                                                         \
    {                                                                                   \
        __half* Ad = smh + (stage) * STAGE_H;                                           \
        __half* Bd = Ad + TILE_H;                                                       \
        const int k0 = (ktile) * BK;                                                    \
        _Pragma("unroll")                                                               \
        for (int i = 0; i < 4; i++) {                                                   \
            int r = ldr + 32 * i;                                                       \
            cp16(&Ad[r * LHW + ldc], &A[(size_t)(by * BM + r) * K + k0 + ldc]);         \
            cp16(&Bd[r * LHW + ldc], &Bt[(size_t)(bx * BN + r) * K + k0 + ldc]);        \
        }                                                                               \
        asm volatile("cp.async.commit_group;\n" ::: "memory");                          \
    }

    LOAD_TILE(0, 0);
    LOAD_TILE(1, 1);

    for (int kt = 0; kt < NT; kt++) {
        if (kt + 2 < NT) asm volatile("cp.async.wait_group 1;\n" ::: "memory");
        else             asm volatile("cp.async.wait_group 0;\n" ::: "memory");
        __syncthreads();

        if (kt + 2 < NT) LOAD_TILE((kt + 2) % STG, kt + 2);

        const uint32_t Ab = sb + (uint32_t)((kt % STG) * STAGE_H) * 2;
        const uint32_t Bb = Ab + TILE_H * 2;

#pragma unroll
        for (int ks = 0; ks < 4; ks++) {
            uint32_t af[4][4], bq[2][4];
#pragma unroll
            for (int mi = 0; mi < 4; mi++)
                ldsm4(af[mi], Ab + (uint32_t)(((wm * 64 + mi * 16 + l15) * LHW) + ks * 16 + lhi8) * 2);
#pragma unroll
            for (int pr = 0; pr < 2; pr++)
                ldsm4(bq[pr], Bb + (uint32_t)(((wn * 32 + pr * 16 + brow) * LHW) + ks * 16 + bk8) * 2);
#pragma unroll
            for (int mi = 0; mi < 4; mi++)
#pragma unroll
                for (int ni = 0; ni < 4; ni++)
                    mma_f16(acc[mi][ni], af[mi], &bq[ni >> 1][(ni & 1) * 2]);
        }
        // no trailing sync: STG=3 + top barrier orders stage reuse
    }

#pragma unroll
    for (int mi = 0; mi < 4; mi++) {
        const int r0 = by * BM + wm * 64 + mi * 16 + lr;
#pragma unroll
        for (int ni = 0; ni < 4; ni++) {
            const int c0 = bx * BN + wn * 32 + ni * 8 + 2 * lc;
            float v0 = acc[mi][ni][0], v1 = acc[mi][ni][1];
            float v2 = acc[mi][ni][2], v3 = acc[mi][ni][3];
            if (MODE == 0) {
                *(float2*)&C[(size_t)r0 * N + c0]       = make_float2(v0, v1);
                *(float2*)&C[(size_t)(r0 + 8) * N + c0] = make_float2(v2, v3);
            } else {
                if (c0 < EMB) {
                    *(__half2*)&qh[(size_t)r0 * EMB + c0]       = __floats2half2_rn(v0, v1);
                    *(__half2*)&qh[(size_t)(r0 + 8) * EMB + c0] = __floats2half2_rn(v2, v3);
                } else if (c0 < 2 * EMB) {
                    const int cc = c0 - EMB;
                    *(__half2*)&kh[(size_t)r0 * EMB + cc]       = __floats2half2_rn(v0, v1);
                    *(__half2*)&kh[(size_t)(r0 + 8) * EMB + cc] = __floats2half2_rn(v2, v3);
                } else {
                    const int cc = c0 - 2 * EMB;
                    const size_t base = (size_t)cc * SEQ;
                    vt[base + r0]           = __float2half_rn(v0);
                    vt[base + SEQ + r0]     = __float2half_rn(v1);
                    vt[base + r0 + 8]       = __float2half_rn(v2);
                    vt[base + SEQ + r0 + 8] = __float2half_rn(v3);
                }
            }
        }
    }
#undef LOAD_TILE
}

// ---------------------------------------------------------------------------
// fp16 attention with ldmatrix fragment loads + per-tile mask specialization.
// ---------------------------------------------------------------------------
__global__ __launch_bounds__(128) void attn_h(const __half* __restrict__ qh,
                                              const __half* __restrict__ kh,
                                              const __half* __restrict__ vt,
                                              __half* __restrict__ ctx) {
    extern __shared__ __half sh[];
    __half* Qs = sh + QS_OFF;
    __half* Ps = sh + PS_OFF;
    const uint32_t sb = smem_u32(sh);

    const int qb = blockIdx.x;
    const int h  = blockIdx.y;
    const int t  = threadIdx.x;
    const int w  = t >> 5;
    const int lane = t & 31;
    const int lr = lane >> 2;
    const int lc = lane & 3;
    const int q0 = qb * 64;
    const int col0 = h * HD;

    const int l15  = lane & 15;
    const int lhi8 = (lane >> 4) * 8;
    const int brow = ((lane >> 4) << 3) + (lane & 7);
    const int bk8  = ((lane >> 3) & 1) * 8;

#define LOADKV(s, kt)                                                                   \
    {                                                                                   \
        __half* Kd = sh + KS_OFF + (s) * 64 * LH;                                       \
        __half* Vd = sh + VS_OFF + (s) * 64 * LH;                                       \
        const int kk0 = (kt) * 64;                                                      \
        _Pragma("unroll")                                                               \
        for (int i = 0; i < 4; i++) {                                                   \
            int id = t + 128 * i;                                                       \
            int r = id >> 3, c = (id & 7) << 3;                                         \
            cp16(&Kd[r * LH + c], &kh[(size_t)(kk0 + r) * EMB + col0 + c]);             \
            cp16(&Vd[r * LH + c], &vt[(size_t)(col0 + r) * SEQ + kk0 + c]);             \
        }                                                                               \
        asm volatile("cp.async.commit_group;\n" ::: "memory");                          \
    }

#pragma unroll
    for (int i = 0; i < 4; i++) {
        int id = t + 128 * i;
        int r = id >> 3, c = (id & 7) << 3;
        cp16(&Qs[r * LH + c], &qh[(size_t)(q0 + r) * EMB + col0 + c]);
    }

    float o[8][4];
#pragma unroll
    for (int nt = 0; nt < 8; nt++)
#pragma unroll
        for (int c = 0; c < 4; c++) o[nt][c] = 0.0f;
    float m[2] = {-1e30f, -1e30f};
    float l[2] = {0.0f, 0.0f};

    const int ktlo = (qb >= 4) ? qb - 4 : 0;
    LOADKV(0, ktlo);

    const uint32_t qfb = sb + (uint32_t)(((16 * w + l15) * LH) + lhi8) * 2;
    const uint32_t pfb = qfb + (uint32_t)(PS_OFF) * 2;

    for (int kt = ktlo; kt <= qb; kt++) {
        const int s = (kt - ktlo) & 1;
        const int k0 = kt * 64;
        const int mode = (kt == qb) ? 1 : ((qb >= 4 && kt == qb - 4) ? 2 : 0);

        asm volatile("cp.async.wait_group 0;\n" ::: "memory");
        __syncthreads();

        if (kt < qb) LOADKV(s ^ 1, kt + 1);

        const uint32_t Kb = sb + (uint32_t)((KS_OFF + s * 64 * LH) + (brow * LH) + bk8) * 2;
        const uint32_t Vb = sb + (uint32_t)((VS_OFF + s * 64 * LH) + (brow * LH) + bk8) * 2;

        // S = Q K^T
        float acc[8][4];
#pragma unroll
        for (int nt = 0; nt < 8; nt++)
#pragma unroll
            for (int c = 0; c < 4; c++) acc[nt][c] = 0.0f;

#pragma unroll
        for (int ks = 0; ks < 4; ks++) {
            uint32_t af[4];
            ldsm4(af, qfb + ks * 32);
#pragma unroll
            for (int pr = 0; pr < 4; pr++) {
                uint32_t bq[4];
                ldsm4(bq, Kb + (uint32_t)(pr * 16 * LH) * 2 + ks * 32);
                mma_f16(acc[2 * pr], af, &bq[0]);
                mma_f16(acc[2 * pr + 1], af, &bq[2]);
            }
        }

        // masked online softmax: 2 rows per thread
#pragma unroll
        for (int i = 0; i < 2; i++) {
            const int qi = q0 + 16 * w + lr + 8 * i;
            float sv[16];
            float mt = -1e30f;
#pragma unroll
            for (int nt = 0; nt < 8; nt++) {
#pragma unroll
                for (int c = 0; c < 2; c++) {
                    int kj = k0 + 8 * nt + 2 * lc + c;
                    bool ok = (mode == 0) ||
                              (mode == 1 ? (kj <= qi) : (kj > qi - WIN));
                    float sx = acc[nt][2 * i + c] * 0.125f;
                    sv[nt * 2 + c] = ok ? sx : -1e30f;
                    mt = fmaxf(mt, sv[nt * 2 + c]);
                }
            }
            mt = fmaxf(mt, __shfl_xor_sync(0xffffffffu, mt, 1));
            mt = fmaxf(mt, __shfl_xor_sync(0xffffffffu, mt, 2));

            float alpha = 1.0f;
            if (mt > m[i]) { alpha = __expf(m[i] - mt); m[i] = mt; }

            float ls = 0.0f;
            float p[16];
#pragma unroll
            for (int j = 0; j < 16; j++) {
                p[j] = (sv[j] > -1e29f) ? __expf(sv[j] - m[i]) : 0.0f;
                ls += p[j];
            }
            ls += __shfl_xor_sync(0xffffffffu, ls, 1);
            ls += __shfl_xor_sync(0xffffffffu, ls, 2);

            l[i] = l[i] * alpha + ls;
#pragma unroll
            for (int nt = 0; nt < 8; nt++) {
                o[nt][2 * i]     *= alpha;
                o[nt][2 * i + 1] *= alpha;
                *(__half2*)&Ps[(16 * w + lr + 8 * i) * LH + 8 * nt + 2 * lc] =
                    __floats2half2_rn(p[nt * 2], p[nt * 2 + 1]);
            }
        }
        __syncwarp();

        // O += P V
#pragma unroll
        for (int ks = 0; ks < 4; ks++) {
            uint32_t pa[4];
            ldsm4(pa, pfb + ks * 32);
#pragma unroll
            for (int pr = 0; pr < 4; pr++) {
                uint32_t vq[4];
                ldsm4(vq, Vb + (uint32_t)(pr * 16 * LH) * 2 + ks * 32);
                mma_f16(o[2 * pr], pa, &vq[0]);
                mma_f16(o[2 * pr + 1], pa, &vq[2]);
            }
        }
        __syncwarp();
    }

    // epilogue: normalize, fp16 ctx
    const float inv0 = 1.0f / l[0];
    const float inv1 = 1.0f / l[1];
    const int row0 = q0 + 16 * w + lr;
#pragma unroll
    for (int nt = 0; nt < 8; nt++) {
        int c0 = col0 + 8 * nt + 2 * lc;
        *(__half2*)&ctx[(size_t)row0 * EMB + c0] =
            __floats2half2_rn(o[nt][0] * inv0, o[nt][1] * inv0);
        *(__half2*)&ctx[(size_t)(row0 + 8) * EMB + c0] =
            __floats2half2_rn(o[nt][2] * inv1, o[nt][3] * inv1);
    }
#undef LOADKV
}

// ---------------------------------------------------------------------------
extern "C" void kernel_launch(void* const* d_in, const int* in_sizes, int n_in,
                              void* d_out, int out_size) {
    const float* x     = (const float*)d_in[0];
    const float* w_qkv = (const float*)d_in[2];
    const float* w_out = (const float*)d_in[3];
    float* out = (float*)d_out;

    __half *ah, *wqt, *wot, *qhp, *khp, *vtp, *chp;
    cudaGetSymbolAddress((void**)&ah, g_ah);
    cudaGetSymbolAddress((void**)&wqt, g_wqt);
    cudaGetSymbolAddress((void**)&wot, g_wot);
    cudaGetSymbolAddress((void**)&qhp, g_qh);
    cudaGetSymbolAddress((void**)&khp, g_kh);
    cudaGetSymbolAddress((void**)&vtp, g_vt);
    cudaGetSymbolAddress((void**)&chp, g_ch);

    cudaFuncSetAttribute(attn_h, cudaFuncAttributeMaxDynamicSharedMemorySize, ATTN_SMEM);
    cudaFuncSetAttribute(hgemm<0>, cudaFuncAttributeMaxDynamicSharedMemorySize, GEMM_SMEM);
    cudaFuncSetAttribute(hgemm<1>, cudaFuncAttributeMaxDynamicSharedMemorySize, GEMM_SMEM);

    // 0) prep
    to_half<<<(SEQ * EMB / 4 + 255) / 256, 256>>>((const float4*)x, (__half2*)ah, SEQ * EMB / 4);
    transpose_half<<<dim3(QKV_N / 32, EMB / 32), 256>>>(w_qkv, wqt, EMB, QKV_N);
    transpose_half<<<dim3(EMB / 32, EMB / 32), 256>>>(w_out, wot, EMB, EMB);

    // 1) qkv = x @ w_qkv -> fp16 Q,K + transposed fp16 V
    hgemm<1><<<dim3(QKV_N / BN, SEQ / BM), 256, GEMM_SMEM>>>(
        ah, wqt, nullptr, qhp, khp, vtp, SEQ, QKV_N, EMB);
    // 2) attention -> fp16 ctx
    attn_h<<<dim3(SEQ / 64, NH), 128, ATTN_SMEM>>>(qhp, khp, vtp, chp);
    // 3) out = ctx @ w_out
    hgemm<0><<<dim3(EMB / BN, SEQ / BM), 256, GEMM_SMEM>>>(
        chp, wot, out, nullptr, nullptr, nullptr, SEQ, EMB, EMB);
}

// round 12
// speedup vs baseline: 5.9363x; 1.0223x over previous
#include <cuda_runtime.h>
#include <cuda_fp16.h>
#include <cstdint>

#define SEQ   4096
#define EMB   1024
#define NH    16
#define HD    64
#define WIN   256
#define QKV_N 3072

// ---- fp16 GEMM tiling: 128x128x64, 8 warps (2x4), warp tile 64x32 ----
#define BM 128
#define BN 128
#define BK 64
#define STG 3
#define LHW 72                               // halves per smem row (64 + 8 pad)
#define TILE_H (128 * LHW)
#define STAGE_H (2 * TILE_H)
#define GEMM_SMEM (STG * STAGE_H * 2)

// ---- attention (fp16): strides in halves ----
#define LH 72
#define QS_OFF  0
#define PS_OFF  (64 * LH)
#define KS_OFF  (2 * 64 * LH)
#define VS_OFF  (4 * 64 * LH)
#define ATTN_SMEM ((6 * 64 * LH) * 2)

static __device__ __half g_ah[SEQ * EMB];      // x fp16 [seq][emb]
static __device__ __half g_wqt[QKV_N * EMB];   // w_qkv^T fp16 [N][K]
static __device__ __half g_wot[EMB * EMB];     // w_out^T fp16 [N][K]
static __device__ __half g_qh[SEQ * EMB];      // Q fp16
static __device__ __half g_kh[SEQ * EMB];      // K fp16
static __device__ __half g_vt[EMB * SEQ];      // V fp16 transposed [(h*64+d)][seq]
static __device__ __half g_ch[SEQ * EMB];      // ctx fp16

__device__ __forceinline__ uint32_t smem_u32(const void* p) {
    uint32_t a;
    asm("{ .reg .u64 t; cvta.to.shared.u64 t, %1; cvt.u32.u64 %0, t; }" : "=r"(a) : "l"(p));
    return a;
}
__device__ __forceinline__ void mma_f16(float d[4], const uint32_t a[4], const uint32_t b[2]) {
    asm volatile(
        "mma.sync.aligned.m16n8k16.row.col.f32.f16.f16.f32 "
        "{%0,%1,%2,%3}, {%4,%5,%6,%7}, {%8,%9}, {%0,%1,%2,%3};\n"
        : "+f"(d[0]), "+f"(d[1]), "+f"(d[2]), "+f"(d[3])
        : "r"(a[0]), "r"(a[1]), "r"(a[2]), "r"(a[3]), "r"(b[0]), "r"(b[1]));
}
__device__ __forceinline__ void ldsm4(uint32_t r[4], uint32_t addr) {
    asm volatile("ldmatrix.sync.aligned.m8n8.x4.shared.b16 {%0,%1,%2,%3}, [%4];"
                 : "=r"(r[0]), "=r"(r[1]), "=r"(r[2]), "=r"(r[3]) : "r"(addr));
}
__device__ __forceinline__ void cp16(const void* smem_dst, const void* gsrc) {
    uint32_t saddr = smem_u32(smem_dst);
    asm volatile("cp.async.cg.shared.global [%0], [%1], 16;\n" :: "r"(saddr), "l"(gsrc) : "memory");
}

// ---------------------------------------------------------------------------
__global__ __launch_bounds__(256) void to_half(const float4* __restrict__ src,
                                               __half2* __restrict__ dst, int n4) {
    int i = blockIdx.x * blockDim.x + threadIdx.x;
    if (i < n4) {
        float4 v = src[i];
        dst[2 * i]     = __floats2half2_rn(v.x, v.y);
        dst[2 * i + 1] = __floats2half2_rn(v.z, v.w);
    }
}

__global__ __launch_bounds__(256) void transpose_half(const float* __restrict__ W,
                                                      __half* __restrict__ T,
                                                      int K, int N) {
    __shared__ float tile[32][33];
    const int tx = threadIdx.x & 31, ty = threadIdx.x >> 5;
    const int n0 = blockIdx.x * 32, k0 = blockIdx.y * 32;
#pragma unroll
    for (int i = 0; i < 4; i++)
        tile[ty + 8 * i][tx] = W[(size_t)(k0 + ty + 8 * i) * N + n0 + tx];
    __syncthreads();
#pragma unroll
    for (int i = 0; i < 4; i++)
        T[(size_t)(n0 + ty + 8 * i) * K + k0 + tx] = __float2half_rn(tile[tx][ty + 8 * i]);
}

// ---------------------------------------------------------------------------
// fp16 tensor-core GEMM with ldmatrix fragment loads.
// MODE 0: fp32 C store. MODE 1: qkv split epilogue -> fp16 Q,K + V^T
//         (V^T staged through smem for coalesced stores).
// ---------------------------------------------------------------------------
template <int MODE>
__global__ __launch_bounds__(256, 2) void hgemm(const __half* __restrict__ A,
                                                const __half* __restrict__ Bt,
                                                float* __restrict__ C,
                                                __half* __restrict__ qh,
                                                __half* __restrict__ kh,
                                                __half* __restrict__ vt,
                                                int M, int N, int K) {
    extern __shared__ __half smh[];
    const uint32_t sb = smem_u32(smh);

    const int t    = threadIdx.x;
    const int w    = t >> 5;
    const int lane = t & 31;
    const int wm   = w >> 2;
    const int wn   = w & 3;
    const int lr   = lane >> 2;
    const int lc   = lane & 3;
    const int bx   = blockIdx.x;
    const int by   = blockIdx.y;

    const int l15  = lane & 15;
    const int lhi8 = (lane >> 4) * 8;
    const int brow = ((lane >> 4) << 3) + (lane & 7);
    const int bk8  = ((lane >> 3) & 1) * 8;

    float acc[4][4][4];
#pragma unroll
    for (int i = 0; i < 4; i++)
#pragma unroll
        for (int j = 0; j < 4; j++)
#pragma unroll
            for (int c = 0; c < 4; c++) acc[i][j][c] = 0.0f;

    const int NT = K / BK;
    const int ldr = t >> 3;
    const int ldc = (t & 7) * 8;

#define LOAD_TILE(stage, ktile)                                                         \
    {                                                                                   \
        __half* Ad = smh + (stage) * STAGE_H;                                           \
        __half* Bd = Ad + TILE_H;                                                       \
        const int k0 = (ktile) * BK;                                                    \
        _Pragma("unroll")                                                               \
        for (int i = 0; i < 4; i++) {                                                   \
            int r = ldr + 32 * i;                                                       \
            cp16(&Ad[r * LHW + ldc], &A[(size_t)(by * BM + r) * K + k0 + ldc]);         \
            cp16(&Bd[r * LHW + ldc], &Bt[(size_t)(bx * BN + r) * K + k0 + ldc]);        \
        }                                                                               \
        asm volatile("cp.async.commit_group;\n" ::: "memory");                          \
    }

    LOAD_TILE(0, 0);
    LOAD_TILE(1, 1);

    for (int kt = 0; kt < NT; kt++) {
        if (kt + 2 < NT) asm volatile("cp.async.wait_group 1;\n" ::: "memory");
        else             asm volatile("cp.async.wait_group 0;\n" ::: "memory");
        __syncthreads();

        if (kt + 2 < NT) LOAD_TILE((kt + 2) % STG, kt + 2);

        const uint32_t Ab = sb + (uint32_t)((kt % STG) * STAGE_H) * 2;
        const uint32_t Bb = Ab + TILE_H * 2;

#pragma unroll
        for (int ks = 0; ks < 4; ks++) {
            uint32_t af[4][4], bq[2][4];
#pragma unroll
            for (int mi = 0; mi < 4; mi++)
                ldsm4(af[mi], Ab + (uint32_t)(((wm * 64 + mi * 16 + l15) * LHW) + ks * 16 + lhi8) * 2);
#pragma unroll
            for (int pr = 0; pr < 2; pr++)
                ldsm4(bq[pr], Bb + (uint32_t)(((wn * 32 + pr * 16 + brow) * LHW) + ks * 16 + bk8) * 2);
#pragma unroll
            for (int mi = 0; mi < 4; mi++)
#pragma unroll
                for (int ni = 0; ni < 4; ni++)
                    mma_f16(acc[mi][ni], af[mi], &bq[ni >> 1][(ni & 1) * 2]);
        }
    }

    if (MODE == 1 && bx >= (2 * EMB) / BN) {
        // ---- V tile: transpose through smem, then coalesced V^T stores ----
        __syncthreads();                       // mainloop smem reads done everywhere
        __half* Vt = smh;                      // [128 dims][136 seq-halves]
#pragma unroll
        for (int mi = 0; mi < 4; mi++) {
            const int sl = wm * 64 + mi * 16 + lr;
#pragma unroll
            for (int ni = 0; ni < 4; ni++) {
                const int d0 = wn * 32 + ni * 8 + 2 * lc;
                Vt[d0 * 136 + sl]           = __float2half_rn(acc[mi][ni][0]);
                Vt[(d0 + 1) * 136 + sl]     = __float2half_rn(acc[mi][ni][1]);
                Vt[d0 * 136 + sl + 8]       = __float2half_rn(acc[mi][ni][2]);
                Vt[(d0 + 1) * 136 + sl + 8] = __float2half_rn(acc[mi][ni][3]);
            }
        }
        __syncthreads();
        const int vcol0 = bx * BN - 2 * EMB;   // dim offset within [0,1024)
#pragma unroll
        for (int i = 0; i < 8; i++) {
            int id = t + 256 * i;              // 0..2047
            int row = id >> 4, ch = id & 15;
            *(uint4*)&vt[(size_t)(vcol0 + row) * SEQ + by * BM + ch * 8] =
                *(const uint4*)&Vt[row * 136 + ch * 8];
        }
        return;
    }

#pragma unroll
    for (int mi = 0; mi < 4; mi++) {
        const int r0 = by * BM + wm * 64 + mi * 16 + lr;
#pragma unroll
        for (int ni = 0; ni < 4; ni++) {
            const int c0 = bx * BN + wn * 32 + ni * 8 + 2 * lc;
            float v0 = acc[mi][ni][0], v1 = acc[mi][ni][1];
            float v2 = acc[mi][ni][2], v3 = acc[mi][ni][3];
            if (MODE == 0) {
                *(float2*)&C[(size_t)r0 * N + c0]       = make_float2(v0, v1);
                *(float2*)&C[(size_t)(r0 + 8) * N + c0] = make_float2(v2, v3);
            } else {
                if (c0 < EMB) {
                    *(__half2*)&qh[(size_t)r0 * EMB + c0]       = __floats2half2_rn(v0, v1);
                    *(__half2*)&qh[(size_t)(r0 + 8) * EMB + c0] = __floats2half2_rn(v2, v3);
                } else {
                    const int cc = c0 - EMB;
                    *(__half2*)&kh[(size_t)r0 * EMB + cc]       = __floats2half2_rn(v0, v1);
                    *(__half2*)&kh[(size_t)(r0 + 8) * EMB + cc] = __floats2half2_rn(v2, v3);
                }
            }
        }
    }
#undef LOAD_TILE
}

// ---------------------------------------------------------------------------
// fp16 attention with ldmatrix fragment loads + per-tile mask specialization.
// ---------------------------------------------------------------------------
__global__ __launch_bounds__(128) void attn_h(const __half* __restrict__ qh,
                                              const __half* __restrict__ kh,
                                              const __half* __restrict__ vt,
                                              __half* __restrict__ ctx) {
    extern __shared__ __half sh[];
    __half* Qs = sh + QS_OFF;
    __half* Ps = sh + PS_OFF;
    const uint32_t sb = smem_u32(sh);

    const int qb = blockIdx.x;
    const int h  = blockIdx.y;
    const int t  = threadIdx.x;
    const int w  = t >> 5;
    const int lane = t & 31;
    const int lr = lane >> 2;
    const int lc = lane & 3;
    const int q0 = qb * 64;
    const int col0 = h * HD;

    const int l15  = lane & 15;
    const int lhi8 = (lane >> 4) * 8;
    const int brow = ((lane >> 4) << 3) + (lane & 7);
    const int bk8  = ((lane >> 3) & 1) * 8;

#define LOADKV(s, kt)                                                                   \
    {                                                                                   \
        __half* Kd = sh + KS_OFF + (s) * 64 * LH;                                       \
        __half* Vd = sh + VS_OFF + (s) * 64 * LH;                                       \
        const int kk0 = (kt) * 64;                                                      \
        _Pragma("unroll")                                                               \
        for (int i = 0; i < 4; i++) {                                                   \
            int id = t + 128 * i;                                                       \
            int r = id >> 3, c = (id & 7) << 3;                                         \
            cp16(&Kd[r * LH + c], &kh[(size_t)(kk0 + r) * EMB + col0 + c]);             \
            cp16(&Vd[r * LH + c], &vt[(size_t)(col0 + r) * SEQ + kk0 + c]);             \
        }                                                                               \
        asm volatile("cp.async.commit_group;\n" ::: "memory");                          \
    }

#pragma unroll
    for (int i = 0; i < 4; i++) {
        int id = t + 128 * i;
        int r = id >> 3, c = (id & 7) << 3;
        cp16(&Qs[r * LH + c], &qh[(size_t)(q0 + r) * EMB + col0 + c]);
    }

    float o[8][4];
#pragma unroll
    for (int nt = 0; nt < 8; nt++)
#pragma unroll
        for (int c = 0; c < 4; c++) o[nt][c] = 0.0f;
    float m[2] = {-1e30f, -1e30f};
    float l[2] = {0.0f, 0.0f};

    const int ktlo = (qb >= 4) ? qb - 4 : 0;
    LOADKV(0, ktlo);

    const uint32_t qfb = sb + (uint32_t)(((16 * w + l15) * LH) + lhi8) * 2;
    const uint32_t pfb = qfb + (uint32_t)(PS_OFF) * 2;

    for (int kt = ktlo; kt <= qb; kt++) {
        const int s = (kt - ktlo) & 1;
        const int k0 = kt * 64;
        const int mode = (kt == qb) ? 1 : ((qb >= 4 && kt == qb - 4) ? 2 : 0);

        asm volatile("cp.async.wait_group 0;\n" ::: "memory");
        __syncthreads();

        if (kt < qb) LOADKV(s ^ 1, kt + 1);

        const uint32_t Kb = sb + (uint32_t)((KS_OFF + s * 64 * LH) + (brow * LH) + bk8) * 2;
        const uint32_t Vb = sb + (uint32_t)((VS_OFF + s * 64 * LH) + (brow * LH) + bk8) * 2;

        float acc[8][4];
#pragma unroll
        for (int nt = 0; nt < 8; nt++)
#pragma unroll
            for (int c = 0; c < 4; c++) acc[nt][c] = 0.0f;

#pragma unroll
        for (int ks = 0; ks < 4; ks++) {
            uint32_t af[4];
            ldsm4(af, qfb + ks * 32);
#pragma unroll
            for (int pr = 0; pr < 4; pr++) {
                uint32_t bq[4];
                ldsm4(bq, Kb + (uint32_t)(pr * 16 * LH) * 2 + ks * 32);
                mma_f16(acc[2 * pr], af, &bq[0]);
                mma_f16(acc[2 * pr + 1], af, &bq[2]);
            }
        }

#pragma unroll
        for (int i = 0; i < 2; i++) {
            const int qi = q0 + 16 * w + lr + 8 * i;
            float sv[16];
            float mt = -1e30f;
#pragma unroll
            for (int nt = 0; nt < 8; nt++) {
#pragma unroll
                for (int c = 0; c < 2; c++) {
                    int kj = k0 + 8 * nt + 2 * lc + c;
                    bool ok = (mode == 0) ||
                              (mode == 1 ? (kj <= qi) : (kj > qi - WIN));
                    float sx = acc[nt][2 * i + c] * 0.125f;
                    sv[nt * 2 + c] = ok ? sx : -1e30f;
                    mt = fmaxf(mt, sv[nt * 2 + c]);
                }
            }
            mt = fmaxf(mt, __shfl_xor_sync(0xffffffffu, mt, 1));
            mt = fmaxf(mt, __shfl_xor_sync(0xffffffffu, mt, 2));

            float alpha = 1.0f;
            if (mt > m[i]) { alpha = __expf(m[i] - mt); m[i] = mt; }

            float ls = 0.0f;
            float p[16];
#pragma unroll
            for (int j = 0; j < 16; j++) {
                p[j] = (sv[j] > -1e29f) ? __expf(sv[j] - m[i]) : 0.0f;
                ls += p[j];
            }
            ls += __shfl_xor_sync(0xffffffffu, ls, 1);
            ls += __shfl_xor_sync(0xffffffffu, ls, 2);

            l[i] = l[i] * alpha + ls;
#pragma unroll
            for (int nt = 0; nt < 8; nt++) {
                o[nt][2 * i]     *= alpha;
                o[nt][2 * i + 1] *= alpha;
                *(__half2*)&Ps[(16 * w + lr + 8 * i) * LH + 8 * nt + 2 * lc] =
                    __floats2half2_rn(p[nt * 2], p[nt * 2 + 1]);
            }
        }
        __syncwarp();

#pragma unroll
        for (int ks = 0; ks < 4; ks++) {
            uint32_t pa[4];
            ldsm4(pa, pfb + ks * 32);
#pragma unroll
            for (int pr = 0; pr < 4; pr++) {
                uint32_t vq[4];
                ldsm4(vq, Vb + (uint32_t)(pr * 16 * LH) * 2 + ks * 32);
                mma_f16(o[2 * pr], pa, &vq[0]);
                mma_f16(o[2 * pr + 1], pa, &vq[2]);
            }
        }
        __syncwarp();
    }

    const float inv0 = 1.0f / l[0];
    const float inv1 = 1.0f / l[1];
    const int row0 = q0 + 16 * w + lr;
#pragma unroll
    for (int nt = 0; nt < 8; nt++) {
        int c0 = col0 + 8 * nt + 2 * lc;
        *(__half2*)&ctx[(size_t)row0 * EMB + c0] =
            __floats2half2_rn(o[nt][0] * inv0, o[nt][1] * inv0);
        *(__half2*)&ctx[(size_t)(row0 + 8) * EMB + c0] =
            __floats2half2_rn(o[nt][2] * inv1, o[nt][3] * inv1);
    }
#undef LOADKV
}

// ---------------------------------------------------------------------------
extern "C" void kernel_launch(void* const* d_in, const int* in_sizes, int n_in,
                              void* d_out, int out_size) {
    const float* x     = (const float*)d_in[0];
    const float* w_qkv = (const float*)d_in[2];
    const float* w_out = (const float*)d_in[3];
    float* out = (float*)d_out;

    __half *ah, *wqt, *wot, *qhp, *khp, *vtp, *chp;
    cudaGetSymbolAddress((void**)&ah, g_ah);
    cudaGetSymbolAddress((void**)&wqt, g_wqt);
    cudaGetSymbolAddress((void**)&wot, g_wot);
    cudaGetSymbolAddress((void**)&qhp, g_qh);
    cudaGetSymbolAddress((void**)&khp, g_kh);
    cudaGetSymbolAddress((void**)&vtp, g_vt);
    cudaGetSymbolAddress((void**)&chp, g_ch);

    cudaFuncSetAttribute(attn_h, cudaFuncAttributeMaxDynamicSharedMemorySize, ATTN_SMEM);
    cudaFuncSetAttribute(hgemm<0>, cudaFuncAttributeMaxDynamicSharedMemorySize, GEMM_SMEM);
    cudaFuncSetAttribute(hgemm<1>, cudaFuncAttributeMaxDynamicSharedMemorySize, GEMM_SMEM);

    // 0) prep
    to_half<<<(SEQ * EMB / 4 + 255) / 256, 256>>>((const float4*)x, (__half2*)ah, SEQ * EMB / 4);
    transpose_half<<<dim3(QKV_N / 32, EMB / 32), 256>>>(w_qkv, wqt, EMB, QKV_N);
    transpose_half<<<dim3(EMB / 32, EMB / 32), 256>>>(w_out, wot, EMB, EMB);

    // 1) qkv = x @ w_qkv -> fp16 Q,K + transposed fp16 V (smem-staged)
    hgemm<1><<<dim3(QKV_N / BN, SEQ / BM), 256, GEMM_SMEM>>>(
        ah, wqt, nullptr, qhp, khp, vtp, SEQ, QKV_N, EMB);
    // 2) attention -> fp16 ctx
    attn_h<<<dim3(SEQ / 64, NH), 128, ATTN_SMEM>>>(qhp, khp, vtp, chp);
    // 3) out = ctx @ w_out
    hgemm<0><<<dim3(EMB / BN, SEQ / BM), 256, GEMM_SMEM>>>(
        chp, wot, out, nullptr, nullptr, nullptr, SEQ, EMB, EMB);
}